// round 5
// baseline (speedup 1.0000x reference)
#include <cuda_runtime.h>
#include <cuda_bf16.h>
#include <cstdint>
#include <cstddef>

// Problem constants
constexpr int BB   = 2;
constexpr int SEQ  = 2048;
constexpr int DIMM = 2048;
constexpr int NH   = 32;
constexpr int NKV  = 8;
constexpr int HDIM = 64;
constexpr int MROWS = BB * SEQ;                    // 4096
constexpr int NQKV  = NH * HDIM + 2 * NKV * HDIM;  // 3072
constexpr int KEFF  = 2 * DIMM;                    // 4096 (hi|lo halves)

// ---------------------------------------------------------------------------
// Scratch (device globals; allocation-free rule)
// ---------------------------------------------------------------------------
__device__ __nv_bfloat16 g_xs[MROWS * KEFF];        // split of x          32 MB
__device__ __nv_bfloat16 g_ws_qkv[NQKV * KEFF];     // split wq|wk|wv      24 MB
__device__ __nv_bfloat16 g_ws_o[DIMM * KEFF];       // split wo            16 MB
__device__ __nv_bfloat16 g_attns[MROWS * KEFF];     // attn out hi|lo      32 MB
__device__ float g_qkv[MROWS * NQKV];               // q|k|v fp32          48 MB
// attention inputs, bf16 [hi(64) | lo(64)] per row
__device__ __nv_bfloat16 g_qs[BB * NH * SEQ * 128];   // 32 MB (q prescaled by 1/8)
__device__ __nv_bfloat16 g_ks[BB * NKV * SEQ * 128];  // 8 MB
__device__ __nv_bfloat16 g_vs[BB * NKV * SEQ * 128];  // 8 MB

// ---------------------------------------------------------------------------
// Helpers
// ---------------------------------------------------------------------------
__device__ __forceinline__ uint32_t smem_u32(const void* p) {
    uint32_t a;
    asm("{ .reg .u64 t; cvta.to.shared.u64 t, %1; cvt.u32.u64 %0, t; }" : "=r"(a) : "l"(p));
    return a;
}
__device__ __forceinline__ void cp_async16(uint32_t dst, const void* src) {
    asm volatile("cp.async.cg.shared.global [%0], [%1], 16;" :: "r"(dst), "l"(src));
}
__device__ __forceinline__ void cp_commit() { asm volatile("cp.async.commit_group;" ::: "memory"); }

__device__ __forceinline__ void ldm_x4(uint32_t* r, uint32_t addr) {
    asm volatile("ldmatrix.sync.aligned.m8n8.x4.shared.b16 {%0,%1,%2,%3}, [%4];"
        : "=r"(r[0]), "=r"(r[1]), "=r"(r[2]), "=r"(r[3]) : "r"(addr));
}
__device__ __forceinline__ void ldm_x4_t(uint32_t* r, uint32_t addr) {
    asm volatile("ldmatrix.sync.aligned.m8n8.x4.trans.shared.b16 {%0,%1,%2,%3}, [%4];"
        : "=r"(r[0]), "=r"(r[1]), "=r"(r[2]), "=r"(r[3]) : "r"(addr));
}
__device__ __forceinline__ void mma_16816(float* d, const uint32_t* a, uint32_t b0, uint32_t b1) {
    asm volatile("mma.sync.aligned.m16n8k16.row.col.f32.bf16.bf16.f32 "
        "{%0,%1,%2,%3}, {%4,%5,%6,%7}, {%8,%9}, {%0,%1,%2,%3};"
        : "+f"(d[0]), "+f"(d[1]), "+f"(d[2]), "+f"(d[3])
        : "r"(a[0]), "r"(a[1]), "r"(a[2]), "r"(a[3]), "r"(b0), "r"(b1));
}
__device__ __forceinline__ float ex2f(float x) {
    float r;
    asm("ex2.approx.f32 %0, %1;" : "=f"(r) : "f"(x));
    return r;
}
__device__ __forceinline__ uint32_t prmt_hi(float a, float b) {
    uint32_t r;
    asm("prmt.b32 %0, %1, %2, 0x7632;" : "=r"(r) : "r"(__float_as_uint(a)), "r"(__float_as_uint(b)));
    return r;
}
__device__ __forceinline__ uint32_t pack_bf16(float lo, float hi) {
    uint32_t r;
    asm("cvt.rn.bf16x2.f32 %0, %2, %1;" : "=r"(r) : "f"(lo), "f"(hi));
    return r;
}
__device__ __forceinline__ float trunc_bf(float x) {
    return __uint_as_float(__float_as_uint(x) & 0xffff0000u);
}

// ---------------------------------------------------------------------------
// Split kernel: fp32 [nrows,2048] -> bf16 [row0+nrows, 4096] as [hi|lo]
// ---------------------------------------------------------------------------
__global__ void split_kernel(const float* __restrict__ src, __nv_bfloat16* __restrict__ dst,
                             int row0, int n) {
    int idx = blockIdx.x * blockDim.x + threadIdx.x;
    if (idx * 4 >= n) return;
    float4 v = ((const float4*)src)[idx];
    int row = (idx * 4) >> 11;
    int col = (idx * 4) & 2047;
    float a[4] = {v.x, v.y, v.z, v.w};
    union { __nv_bfloat16 b[4]; uint2 u; } H, L;
#pragma unroll
    for (int j = 0; j < 4; j++) {
        __nv_bfloat16 h = __float2bfloat16(a[j]);
        H.b[j] = h;
        L.b[j] = __float2bfloat16(a[j] - __bfloat162float(h));
    }
    size_t base = (size_t)(row0 + row) * KEFF + col;
    *(uint2*)(dst + base) = H.u;
    *(uint2*)(dst + base + 2048) = L.u;
}

// ---------------------------------------------------------------------------
// bf16-split NT GEMM via mma.sync:  C[M,N] = A[M,2048]*B[N,2048]^T (fp32 acc)
// CTA tile 128x256, 256 thr, warp grid 2x4 (warp tile 64x64), K-chunk 32,
// 4-stage cp.async pipeline, smem row stride 80B.
// grid = (Ntot/256, M/128).
// ---------------------------------------------------------------------------
constexpr int TILE_A  = 128 * 80;               // 10240 B
constexpr int TILE_B2 = 256 * 80;               // 20480 B
constexpr int STAGE_B = TILE_A + TILE_B2;       // 30720 B
constexpr int NSTG    = 4;
constexpr int GEMM_SMEM = NSTG * STAGE_B;       // 122880 B
constexpr int NCH = 192;                        // 3 segments * 64 chunks of K=32

__global__ __launch_bounds__(256, 1)
void gemm_mma(const __nv_bfloat16* __restrict__ A, const __nv_bfloat16* __restrict__ B,
              float* __restrict__ C, int Ntot) {
    extern __shared__ __align__(128) char dsm[];
    const int tid = threadIdx.x;
    const int wid = tid >> 5;
    const int L = tid & 31;
    const int wm = (wid >> 2) * 64;     // 0,64
    const int wn = (wid & 3) * 64;      // 0,64,128,192
    const uint32_t dynbase = smem_u32(dsm);

    const int bm = blockIdx.y * 128;
    const int bn = blockIdx.x * 256;
    const __nv_bfloat16* Abase = A + (size_t)bm * KEFF;
    const __nv_bfloat16* Bbase = B + (size_t)bn * KEFF;

    float acc[4][8][4];
#pragma unroll
    for (int i = 0; i < 4; i++)
#pragma unroll
        for (int j = 0; j < 8; j++)
#pragma unroll
            for (int q = 0; q < 4; q++) acc[i][j][q] = 0.f;

    auto load_stage = [&](int s, int c) {
        const int seg = c >> 6;
        const int kk = (c & 63) * 32;
        const int aoff = (seg == 2 ? 2048 : 0) + kk;
        const int boff = (seg == 1 ? 2048 : 0) + kk;
        const uint32_t sb = dynbase + s * STAGE_B;
#pragma unroll
        for (int u = 0; u < 2; u++) {          // A: 128 rows x 4 x 16B
            int e = tid + u * 256;
            int row = e >> 2, ch = e & 3;
            cp_async16(sb + row * 80 + ch * 16,
                       Abase + (size_t)row * KEFF + aoff + ch * 8);
        }
#pragma unroll
        for (int u = 0; u < 4; u++) {          // B: 256 rows x 4 x 16B
            int e = tid + u * 256;
            int row = e >> 2, ch = e & 3;
            cp_async16(sb + TILE_A + row * 80 + ch * 16,
                       Bbase + (size_t)row * KEFF + boff + ch * 8);
        }
    };

    load_stage(0, 0); cp_commit();
    load_stage(1, 1); cp_commit();
    load_stage(2, 2); cp_commit();

    const uint32_t lrow = L & 15;
    const uint32_t lcol16 = (L >> 4) * 16;

    for (int i = 0; i < NCH; i++) {
        if (i + 3 < NCH) load_stage((i + 3) & 3, i + 3);
        cp_commit();
        asm volatile("cp.async.wait_group 3;" ::: "memory");
        __syncthreads();

        const uint32_t sb = dynbase + (i & 3) * STAGE_B;
#pragma unroll
        for (int ks = 0; ks < 2; ks++) {
            uint32_t a[4][4], b[4][4];
#pragma unroll
            for (int am = 0; am < 4; am++)
                ldm_x4(a[am], sb + (wm + am * 16 + lrow) * 80 + lcol16 + ks * 32);
#pragma unroll
            for (int g = 0; g < 4; g++)
                ldm_x4(b[g], sb + TILE_A + (wn + g * 16 + lrow) * 80 + lcol16 + ks * 32);
#pragma unroll
            for (int am = 0; am < 4; am++)
#pragma unroll
                for (int an = 0; an < 8; an++)
                    mma_16816(acc[am][an], a[am], b[an >> 1][an & 1], b[an >> 1][2 + (an & 1)]);
        }
        __syncthreads();
    }

#pragma unroll
    for (int am = 0; am < 4; am++) {
        int row = bm + wm + am * 16 + (L >> 2);
#pragma unroll
        for (int an = 0; an < 8; an++) {
            int col = bn + wn + an * 8 + (L & 3) * 2;
            float2 lo = make_float2(acc[am][an][0], acc[am][an][1]);
            float2 hi = make_float2(acc[am][an][2], acc[am][an][3]);
            *(float2*)(C + (size_t)row * Ntot + col) = lo;
            *(float2*)(C + (size_t)(row + 8) * Ntot + col) = hi;
        }
    }
}

// ---------------------------------------------------------------------------
// Fused RoPE + hi/lo split for attention inputs.
// ---------------------------------------------------------------------------
__global__ __launch_bounds__(256) void rope_split(const float* __restrict__ qkv,
                                                  const float* __restrict__ freqs) {
    const int ml = blockIdx.x;            // b*SEQ + l
    const int l = ml & (SEQ - 1);
    const int b = ml >> 11;
    const float* row = qkv + (size_t)ml * NQKV;

#pragma unroll
    for (int it = 0; it < 6; it++) {
        int u = threadIdx.x + it * 256;
        float v0, v1;
        __nv_bfloat16* dst;
        if (u < 1024) {                   // q
            int h = u >> 5, p = u & 31;
            float2 t = *(const float2*)(row + h * 64 + 2 * p);
            float c = freqs[l * 32 + p];
            float s = freqs[SEQ * 32 + l * 32 + p];
            v0 = (t.x * c - t.y * s) * 0.125f;
            v1 = (t.x * s + t.y * c) * 0.125f;
            dst = g_qs + ((size_t)(b * NH + h) * SEQ + l) * 128 + 2 * p;
        } else if (u < 1280) {            // k
            int u2 = u - 1024;
            int kh = u2 >> 5, p = u2 & 31;
            float2 t = *(const float2*)(row + 2048 + kh * 64 + 2 * p);
            float c = freqs[l * 32 + p];
            float s = freqs[SEQ * 32 + l * 32 + p];
            v0 = t.x * c - t.y * s;
            v1 = t.x * s + t.y * c;
            dst = g_ks + ((size_t)(b * NKV + kh) * SEQ + l) * 128 + 2 * p;
        } else {                          // v
            int u2 = u - 1280;
            int kh = u2 >> 5, p = u2 & 31;
            float2 t = *(const float2*)(row + 2560 + kh * 64 + 2 * p);
            v0 = t.x; v1 = t.y;
            dst = g_vs + ((size_t)(b * NKV + kh) * SEQ + l) * 128 + 2 * p;
        }
        __nv_bfloat16 h0 = __float2bfloat16(v0);
        __nv_bfloat16 h1 = __float2bfloat16(v1);
        dst[0] = h0;
        dst[1] = h1;
        dst[64] = __float2bfloat16(v0 - __bfloat162float(h0));
        dst[65] = __float2bfloat16(v1 - __bfloat162float(h1));
    }
}

// ---------------------------------------------------------------------------
// Tensor-core causal flash attention, bf16 hi/lo splits both sides.
// Epilogue writes bf16 hi|lo directly into g_attns (input of O projection).
// ---------------------------------------------------------------------------
constexpr int AT_STR = 144;
constexpr int AT_ARR = 64 * AT_STR;
constexpr int AT_SMEM = 6 * AT_ARR;                // 55296
constexpr float LOG2E = 1.4426950408889634f;

__global__ __launch_bounds__(128, 2)
void flash_attn_mma(const __nv_bfloat16* __restrict__ Qs,
                    const __nv_bfloat16* __restrict__ Ks,
                    const __nv_bfloat16* __restrict__ Vs) {
    extern __shared__ __align__(128) char fsm[];
    const uint32_t sQh = smem_u32(fsm);
    const uint32_t sQl = sQh + AT_ARR;
    const uint32_t sKh = sQh + 2 * AT_ARR;
    const uint32_t sKl = sQh + 3 * AT_ARR;
    const uint32_t sVh = sQh + 4 * AT_ARR;
    const uint32_t sVl = sQh + 5 * AT_ARR;

    const int tid = threadIdx.x;
    const int wid = tid >> 5;
    const int L = tid & 31;
    const int wm = wid * 16;
    const uint32_t lrow = L & 15;
    const uint32_t lcol16 = (L >> 4) * 16;

    const int m0 = blockIdx.x * 64;
    const int h = blockIdx.y;
    const int b = blockIdx.z;
    const int kvh = h >> 2;

    const __nv_bfloat16* qsrc = Qs + ((size_t)(b * NH + h) * SEQ + m0) * 128;
#pragma unroll
    for (int u = 0; u < 8; u++) {
        int e = tid + u * 128;
        int row = e >> 4, ch = e & 15;
        uint32_t dst = (ch < 8) ? (sQh + row * AT_STR + ch * 16)
                                : (sQl + row * AT_STR + (ch - 8) * 16);
        cp_async16(dst, qsrc + (size_t)row * 128 + ch * 8);
    }
    cp_commit();
    asm volatile("cp.async.wait_group 0;" ::: "memory");
    __syncthreads();

    uint32_t qh[4][4], ql[4][4];
#pragma unroll
    for (int kg = 0; kg < 4; kg++) {
        ldm_x4(qh[kg], sQh + (wm + lrow) * AT_STR + kg * 32 + lcol16);
        ldm_x4(ql[kg], sQl + (wm + lrow) * AT_STR + kg * 32 + lcol16);
    }

    float O[8][4];
#pragma unroll
    for (int i = 0; i < 8; i++)
#pragma unroll
        for (int j = 0; j < 4; j++) O[i][j] = 0.f;
    float mr0 = -1e30f, mr1 = -1e30f, lr0 = 0.f, lr1 = 0.f;

    const __nv_bfloat16* ksrc = Ks + ((size_t)(b * NKV + kvh) * SEQ) * 128;
    const __nv_bfloat16* vsrc = Vs + ((size_t)(b * NKV + kvh) * SEQ) * 128;

    const int nT = m0 / 64 + 1;
    for (int t = 0; t < nT; t++) {
        const int n0 = t * 64;
        __syncthreads();
#pragma unroll
        for (int u = 0; u < 8; u++) {
            int e = tid + u * 128;
            int row = e >> 4, ch = e & 15;
            uint32_t kd = (ch < 8) ? (sKh + row * AT_STR + ch * 16)
                                   : (sKl + row * AT_STR + (ch - 8) * 16);
            uint32_t vd = (ch < 8) ? (sVh + row * AT_STR + ch * 16)
                                   : (sVl + row * AT_STR + (ch - 8) * 16);
            cp_async16(kd, ksrc + (size_t)(n0 + row) * 128 + ch * 8);
            cp_async16(vd, vsrc + (size_t)(n0 + row) * 128 + ch * 8);
        }
        cp_commit();
        asm volatile("cp.async.wait_group 0;" ::: "memory");
        __syncthreads();

        float S[8][4];
#pragma unroll
        for (int i = 0; i < 8; i++)
#pragma unroll
            for (int j = 0; j < 4; j++) S[i][j] = 0.f;

#pragma unroll
        for (int kg = 0; kg < 4; kg++) {
            uint32_t kfh[4][4], kfl[4][4];
#pragma unroll
            for (int nn = 0; nn < 4; nn++) {
                ldm_x4(kfh[nn], sKh + (nn * 16 + lrow) * AT_STR + kg * 32 + lcol16);
                ldm_x4(kfl[nn], sKl + (nn * 16 + lrow) * AT_STR + kg * 32 + lcol16);
            }
#pragma unroll
            for (int ng = 0; ng < 8; ng++) {
                int nn = ng >> 1, e = ng & 1;
                mma_16816(S[ng], qh[kg], kfh[nn][e], kfh[nn][2 + e]);
                mma_16816(S[ng], qh[kg], kfl[nn][e], kfl[nn][2 + e]);
                mma_16816(S[ng], ql[kg], kfh[nn][e], kfh[nn][2 + e]);
            }
        }

        const int r0 = wm + (L >> 2);
        const int r1 = r0 + 8;
        if (t == nT - 1) {
#pragma unroll
            for (int ng = 0; ng < 8; ng++) {
                int c0 = ng * 8 + (L & 3) * 2;
                if (c0 > r0)     S[ng][0] = -1e30f;
                if (c0 + 1 > r0) S[ng][1] = -1e30f;
                if (c0 > r1)     S[ng][2] = -1e30f;
                if (c0 + 1 > r1) S[ng][3] = -1e30f;
            }
        }

        float t0 = -1e30f, t1 = -1e30f;
#pragma unroll
        for (int ng = 0; ng < 8; ng++) {
            t0 = fmaxf(t0, fmaxf(S[ng][0], S[ng][1]));
            t1 = fmaxf(t1, fmaxf(S[ng][2], S[ng][3]));
        }
        t0 = fmaxf(t0, __shfl_xor_sync(0xffffffffu, t0, 1));
        t0 = fmaxf(t0, __shfl_xor_sync(0xffffffffu, t0, 2));
        t1 = fmaxf(t1, __shfl_xor_sync(0xffffffffu, t1, 1));
        t1 = fmaxf(t1, __shfl_xor_sync(0xffffffffu, t1, 2));

        float mn0 = fmaxf(mr0, t0), mn1 = fmaxf(mr1, t1);
        float corr0 = ex2f((mr0 - mn0) * LOG2E);
        float corr1 = ex2f((mr1 - mn1) * LOG2E);
        lr0 *= corr0; lr1 *= corr1;
#pragma unroll
        for (int ng = 0; ng < 8; ng++) {
            O[ng][0] *= corr0; O[ng][1] *= corr0;
            O[ng][2] *= corr1; O[ng][3] *= corr1;
        }
        mr0 = mn0; mr1 = mn1;
        const float mb0 = mn0 * LOG2E, mb1 = mn1 * LOG2E;

        uint32_t pah[4][4], pal[4][4];
        float s0 = 0.f, s1 = 0.f;
#pragma unroll
        for (int kg = 0; kg < 4; kg++) {
            float p[8];
#pragma unroll
            for (int e = 0; e < 2; e++) {
                const int g = 2 * kg + e;
                p[4 * e + 0] = ex2f(fmaf(S[g][0], LOG2E, -mb0));
                p[4 * e + 1] = ex2f(fmaf(S[g][1], LOG2E, -mb0));
                p[4 * e + 2] = ex2f(fmaf(S[g][2], LOG2E, -mb1));
                p[4 * e + 3] = ex2f(fmaf(S[g][3], LOG2E, -mb1));
                s0 += p[4 * e] + p[4 * e + 1];
                s1 += p[4 * e + 2] + p[4 * e + 3];
            }
            pah[kg][0] = prmt_hi(p[0], p[1]);
            pah[kg][1] = prmt_hi(p[2], p[3]);
            pah[kg][2] = prmt_hi(p[4], p[5]);
            pah[kg][3] = prmt_hi(p[6], p[7]);
            pal[kg][0] = pack_bf16(p[0] - trunc_bf(p[0]), p[1] - trunc_bf(p[1]));
            pal[kg][1] = pack_bf16(p[2] - trunc_bf(p[2]), p[3] - trunc_bf(p[3]));
            pal[kg][2] = pack_bf16(p[4] - trunc_bf(p[4]), p[5] - trunc_bf(p[5]));
            pal[kg][3] = pack_bf16(p[6] - trunc_bf(p[6]), p[7] - trunc_bf(p[7]));
        }
        s0 += __shfl_xor_sync(0xffffffffu, s0, 1);
        s0 += __shfl_xor_sync(0xffffffffu, s0, 2);
        s1 += __shfl_xor_sync(0xffffffffu, s1, 1);
        s1 += __shfl_xor_sync(0xffffffffu, s1, 2);
        lr0 += s0; lr1 += s1;

#pragma unroll
        for (int kg = 0; kg < 4; kg++) {
            uint32_t vfh[4][4], vfl[4][4];
#pragma unroll
            for (int cp = 0; cp < 4; cp++) {
                ldm_x4_t(vfh[cp], sVh + (kg * 16 + lrow) * AT_STR + cp * 32 + lcol16);
                ldm_x4_t(vfl[cp], sVl + (kg * 16 + lrow) * AT_STR + cp * 32 + lcol16);
            }
#pragma unroll
            for (int cp = 0; cp < 4; cp++) {
#pragma unroll
                for (int e = 0; e < 2; e++) {
                    const int ng = 2 * cp + e;
                    mma_16816(O[ng], pah[kg], vfh[cp][2 * e], vfh[cp][2 * e + 1]);
                    mma_16816(O[ng], pah[kg], vfl[cp][2 * e], vfl[cp][2 * e + 1]);
                    mma_16816(O[ng], pal[kg], vfh[cp][2 * e], vfh[cp][2 * e + 1]);
                }
            }
        }
    }

    // ---- write out: bf16 hi|lo directly into g_attns ----
    const float inv0 = 1.f / lr0;
    const float inv1 = 1.f / lr1;
    const int r0 = wm + (L >> 2);
    __nv_bfloat16* a0 = g_attns + (size_t)(b * SEQ + m0 + r0) * KEFF + h * 64 + (L & 3) * 2;
    __nv_bfloat16* a1 = g_attns + (size_t)(b * SEQ + m0 + r0 + 8) * KEFF + h * 64 + (L & 3) * 2;
#pragma unroll
    for (int ng = 0; ng < 8; ng++) {
        float x0 = O[ng][0] * inv0, x1 = O[ng][1] * inv0;
        float y0 = O[ng][2] * inv1, y1 = O[ng][3] * inv1;
        __nv_bfloat16 h00 = __float2bfloat16(x0), h01 = __float2bfloat16(x1);
        __nv_bfloat16 h10 = __float2bfloat16(y0), h11 = __float2bfloat16(y1);
        union { __nv_bfloat16 b[2]; uint32_t u; } H0, L0, H1, L1;
        H0.b[0] = h00; H0.b[1] = h01;
        L0.b[0] = __float2bfloat16(x0 - __bfloat162float(h00));
        L0.b[1] = __float2bfloat16(x1 - __bfloat162float(h01));
        H1.b[0] = h10; H1.b[1] = h11;
        L1.b[0] = __float2bfloat16(y0 - __bfloat162float(h10));
        L1.b[1] = __float2bfloat16(y1 - __bfloat162float(h11));
        *(uint32_t*)(a0 + ng * 8) = H0.u;
        *(uint32_t*)(a0 + ng * 8 + 2048) = L0.u;
        *(uint32_t*)(a1 + ng * 8) = H1.u;
        *(uint32_t*)(a1 + ng * 8 + 2048) = L1.u;
    }
}

// ---------------------------------------------------------------------------
extern "C" void kernel_launch(void* const* d_in, const int* in_sizes, int n_in,
                              void* d_out, int out_size) {
    const float* x     = (const float*)d_in[0];
    const float* freqs = (const float*)d_in[1];
    const float* wq    = (const float*)d_in[2];
    const float* wk    = (const float*)d_in[3];
    const float* wv    = (const float*)d_in[4];
    const float* wo    = (const float*)d_in[5];
    float* out = (float*)d_out;

    __nv_bfloat16 *xs, *wsqkv, *wso, *attns, *qs, *ks, *vs;
    float *qkv;
    cudaGetSymbolAddress((void**)&xs, g_xs);
    cudaGetSymbolAddress((void**)&wsqkv, g_ws_qkv);
    cudaGetSymbolAddress((void**)&wso, g_ws_o);
    cudaGetSymbolAddress((void**)&attns, g_attns);
    cudaGetSymbolAddress((void**)&qkv, g_qkv);
    cudaGetSymbolAddress((void**)&qs, g_qs);
    cudaGetSymbolAddress((void**)&ks, g_ks);
    cudaGetSymbolAddress((void**)&vs, g_vs);

    static bool attr_done = false;
    if (!attr_done) {
        cudaFuncSetAttribute(gemm_mma, cudaFuncAttributeMaxDynamicSharedMemorySize, GEMM_SMEM);
        cudaFuncSetAttribute(flash_attn_mma, cudaFuncAttributeMaxDynamicSharedMemorySize, AT_SMEM);
        attr_done = true;
    }

    // 1) splits of x + weights
    {
        int n = MROWS * DIMM;
        split_kernel<<<(n / 4 + 255) / 256, 256>>>(x, xs, 0, n);
        n = 2048 * DIMM;
        split_kernel<<<(n / 4 + 255) / 256, 256>>>(wq, wsqkv, 0, n);
        n = 512 * DIMM;
        split_kernel<<<(n / 4 + 255) / 256, 256>>>(wk, wsqkv, 2048, n);
        split_kernel<<<(n / 4 + 255) / 256, 256>>>(wv, wsqkv, 2560, n);
        n = 2048 * DIMM;
        split_kernel<<<(n / 4 + 255) / 256, 256>>>(wo, wso, 0, n);
    }

    // 2) fused QKV projection
    gemm_mma<<<dim3(NQKV / 256, MROWS / 128), 256, GEMM_SMEM>>>(xs, wsqkv, qkv, NQKV);

    // 3) RoPE + split attention inputs
    rope_split<<<MROWS, 256>>>(qkv, freqs);

    // 4) tensor-core attention (writes g_attns hi|lo directly)
    flash_attn_mma<<<dim3(SEQ / 64, NH, BB), 128, AT_SMEM>>>(qs, ks, vs);

    // 5) O projection
    gemm_mma<<<dim3(DIMM / 256, MROWS / 128), 256, GEMM_SMEM>>>(attns, wso, out, DIMM);
}

// round 7
// speedup vs baseline: 1.7320x; 1.7320x over previous
#include <cuda_runtime.h>
#include <cuda_bf16.h>
#include <cstdint>
#include <cstddef>

// Problem constants
constexpr int BB   = 2;
constexpr int SEQ  = 2048;
constexpr int DIMM = 2048;
constexpr int NH   = 32;
constexpr int NKV  = 8;
constexpr int HDIM = 64;
constexpr int MROWS = BB * SEQ;                    // 4096
constexpr int NQKV  = NH * HDIM + 2 * NKV * HDIM;  // 3072

// ---------------------------------------------------------------------------
// Scratch (device globals; allocation-free rule)
// Packed tf32 operands in MMA-fragment order:
//  A-pack:  [mb=row/16][kc=k/8][lane][4 words]   (a0..a3 of m16n8k8)
//  B-pack:  [nb=n/8][kc16=k/16][lane][4 words]   (b0,b1 of two k8 chunks)
// ---------------------------------------------------------------------------
__device__ uint32_t g_xt[MROWS * DIMM];             // packed x           32 MB
__device__ uint32_t g_wqkvt[NQKV * DIMM];           // packed wq|wk|wv    24 MB
__device__ uint32_t g_wot[DIMM * DIMM];             // packed wo          16 MB
__device__ uint32_t g_at[MROWS * DIMM];             // packed attn out    32 MB
__device__ float g_qkv[MROWS * NQKV];               // q|k|v fp32         48 MB
__device__ float g_attn[MROWS * NH * HDIM];         // attn out fp32      32 MB
// attention inputs, bf16 [hi(64) | lo(64)] per row
__device__ __nv_bfloat16 g_qs[BB * NH * SEQ * 128];   // 32 MB (q prescaled by 1/8)
__device__ __nv_bfloat16 g_ks[BB * NKV * SEQ * 128];  // 8 MB
__device__ __nv_bfloat16 g_vs[BB * NKV * SEQ * 128];  // 8 MB

// ---------------------------------------------------------------------------
// Helpers
// ---------------------------------------------------------------------------
__device__ __forceinline__ uint32_t smem_u32(const void* p) {
    uint32_t a;
    asm("{ .reg .u64 t; cvta.to.shared.u64 t, %1; cvt.u32.u64 %0, t; }" : "=r"(a) : "l"(p));
    return a;
}
__device__ __forceinline__ void cp_async16(uint32_t dst, const void* src) {
    asm volatile("cp.async.cg.shared.global [%0], [%1], 16;" :: "r"(dst), "l"(src));
}
__device__ __forceinline__ void cp_commit() { asm volatile("cp.async.commit_group;" ::: "memory"); }

__device__ __forceinline__ void lds128(uint32_t* r, uint32_t addr) {
    asm volatile("ld.shared.v4.b32 {%0,%1,%2,%3}, [%4];"
        : "=r"(r[0]), "=r"(r[1]), "=r"(r[2]), "=r"(r[3]) : "r"(addr));
}
__device__ __forceinline__ void ldm_x4(uint32_t* r, uint32_t addr) {
    asm volatile("ldmatrix.sync.aligned.m8n8.x4.shared.b16 {%0,%1,%2,%3}, [%4];"
        : "=r"(r[0]), "=r"(r[1]), "=r"(r[2]), "=r"(r[3]) : "r"(addr));
}
__device__ __forceinline__ void ldm_x4_t(uint32_t* r, uint32_t addr) {
    asm volatile("ldmatrix.sync.aligned.m8n8.x4.trans.shared.b16 {%0,%1,%2,%3}, [%4];"
        : "=r"(r[0]), "=r"(r[1]), "=r"(r[2]), "=r"(r[3]) : "r"(addr));
}
__device__ __forceinline__ void mma_16816(float* d, const uint32_t* a, uint32_t b0, uint32_t b1) {
    asm volatile("mma.sync.aligned.m16n8k16.row.col.f32.bf16.bf16.f32 "
        "{%0,%1,%2,%3}, {%4,%5,%6,%7}, {%8,%9}, {%0,%1,%2,%3};"
        : "+f"(d[0]), "+f"(d[1]), "+f"(d[2]), "+f"(d[3])
        : "r"(a[0]), "r"(a[1]), "r"(a[2]), "r"(a[3]), "r"(b0), "r"(b1));
}
__device__ __forceinline__ void mma_tf32(float* d, const uint32_t* a, uint32_t b0, uint32_t b1) {
    asm volatile("mma.sync.aligned.m16n8k8.row.col.f32.tf32.tf32.f32 "
        "{%0,%1,%2,%3}, {%4,%5,%6,%7}, {%8,%9}, {%0,%1,%2,%3};"
        : "+f"(d[0]), "+f"(d[1]), "+f"(d[2]), "+f"(d[3])
        : "r"(a[0]), "r"(a[1]), "r"(a[2]), "r"(a[3]), "r"(b0), "r"(b1));
}
__device__ __forceinline__ uint32_t f2tf32(float x) {
    uint32_t r;
    asm("cvt.rna.tf32.f32 %0, %1;" : "=r"(r) : "f"(x));
    return r;
}
__device__ __forceinline__ float ex2f(float x) {
    float r;
    asm("ex2.approx.f32 %0, %1;" : "=f"(r) : "f"(x));
    return r;
}
__device__ __forceinline__ uint32_t prmt_hi(float a, float b) {
    uint32_t r;
    asm("prmt.b32 %0, %1, %2, 0x7632;" : "=r"(r) : "r"(__float_as_uint(a)), "r"(__float_as_uint(b)));
    return r;
}
__device__ __forceinline__ uint32_t pack_bf16(float lo, float hi) {
    uint32_t r;
    asm("cvt.rn.bf16x2.f32 %0, %2, %1;" : "=r"(r) : "f"(lo), "f"(hi));
    return r;
}
__device__ __forceinline__ float trunc_bf(float x) {
    return __uint_as_float(__float_as_uint(x) & 0xffff0000u);
}

// ---------------------------------------------------------------------------
// pack_a: fp32 [rows][2048] row-major -> tf32 A-fragment pack.
// Per mb block: 256 kc * 32 lanes, one uint4 each (= 32768 words = 16x2048).
// ---------------------------------------------------------------------------
__global__ __launch_bounds__(256) void pack_a(const float* __restrict__ src,
                                              uint32_t* __restrict__ dst,
                                              int mb0, int nmb) {
    int idx = blockIdx.x * 256 + threadIdx.x;
    if (idx >= nmb * 8192) return;
    int lane = idx & 31;
    int r = lane >> 2, c = lane & 3;
    int kc = (idx >> 5) & 255;
    int mb = (idx >> 13) + mb0;
    const float* s = src + (size_t)mb * 16 * 2048 + kc * 8;
    uint4 o;
    o.x = f2tf32(s[(size_t)r * 2048 + c]);
    o.y = f2tf32(s[(size_t)(r + 8) * 2048 + c]);
    o.z = f2tf32(s[(size_t)r * 2048 + c + 4]);
    o.w = f2tf32(s[(size_t)(r + 8) * 2048 + c + 4]);
    ((uint4*)dst)[(size_t)mb * 8192 + (idx & 8191)] = o;
}

// ---------------------------------------------------------------------------
// pack_b: weights [N][2048] row-major -> tf32 B-fragment pack.
// Per nb block: 128 kc16 * 32 lanes uint4 (= 16384 words = 8x2048).
// ---------------------------------------------------------------------------
__global__ __launch_bounds__(256) void pack_b(const float* __restrict__ src,
                                              uint32_t* __restrict__ dst, int total) {
    int idx = blockIdx.x * 256 + threadIdx.x;
    if (idx >= total) return;
    int lane = idx & 31;
    int kc16 = (idx >> 5) & 127;
    int nb = idx >> 12;
    int k = kc16 * 16 + (lane & 3);
    int n = nb * 8 + (lane >> 2);
    const float* s = src + (size_t)n * 2048 + k;
    uint4 o = { f2tf32(s[0]), f2tf32(s[4]), f2tf32(s[8]), f2tf32(s[12]) };
    ((uint4*)dst)[idx] = o;
}

__global__ __launch_bounds__(256) void pack_b_qkv(const float* __restrict__ wq,
                                                  const float* __restrict__ wk,
                                                  const float* __restrict__ wv,
                                                  uint32_t* __restrict__ dst, int total) {
    int idx = blockIdx.x * 256 + threadIdx.x;
    if (idx >= total) return;
    int lane = idx & 31;
    int kc16 = (idx >> 5) & 127;
    int nb = idx >> 12;
    int k = kc16 * 16 + (lane & 3);
    int n = nb * 8 + (lane >> 2);
    const float* s;
    if (n < 2048)      s = wq + (size_t)n * 2048 + k;
    else if (n < 2560) s = wk + (size_t)(n - 2048) * 2048 + k;
    else               s = wv + (size_t)(n - 2560) * 2048 + k;
    uint4 o = { f2tf32(s[0]), f2tf32(s[4]), f2tf32(s[8]), f2tf32(s[12]) };
    ((uint4*)dst)[idx] = o;
}

// ---------------------------------------------------------------------------
// tf32 GEMM: C[M,N] = A[M,2048] * B[N,2048]^T, operands fragment-packed.
// CTA 128x128, 256 thr, warps 2x4 (warp tile 64x32), K-chunk 32,
// 3-stage cp.async pipeline (32KB/stage), 2 CTAs/SM.
// ---------------------------------------------------------------------------
constexpr int TSTAGE = 32768;
constexpr int GSMEM  = 3 * TSTAGE;                 // 98304

__global__ __launch_bounds__(256, 2)
void gemm_tf32(const uint32_t* __restrict__ A, const uint32_t* __restrict__ B,
               float* __restrict__ C, int Ntot) {
    extern __shared__ __align__(128) char dsm[];
    const int tid = threadIdx.x;
    const int wid = tid >> 5;
    const int L = tid & 31;
    const uint32_t base = smem_u32(dsm);
    const int bm = blockIdx.y * 128;
    const int bn = blockIdx.x * 128;
    const uint32_t* Ab = A + (size_t)(bm >> 4) * 32768;  // per mb block: 32768 words
    const uint32_t* Bb = B + (size_t)(bn >> 3) * 16384;  // per nb block: 16384 words

    float acc[4][4][4];
#pragma unroll
    for (int i = 0; i < 4; i++)
#pragma unroll
        for (int j = 0; j < 4; j++)
#pragma unroll
            for (int q = 0; q < 4; q++) acc[i][j][q] = 0.f;

    auto load_stage = [&](int s, int c) {        // K-chunk c covers k = c*32..+31
        const uint32_t sb = base + s * TSTAGE;
#pragma unroll
        for (int u = 0; u < 4; u++) {            // A: 1024 x 16B
            int e = tid + u * 256;
            int lane = e & 31, kc = (e >> 5) & 3, mb = e >> 7;
            cp_async16(sb + e * 16,
                       Ab + (((size_t)mb * 256 + c * 4 + kc) * 32 + lane) * 4);
        }
#pragma unroll
        for (int u = 0; u < 4; u++) {            // B: 1024 x 16B
            int e = tid + u * 256;
            int lane = e & 31, kc16 = (e >> 5) & 1, nb = e >> 6;
            cp_async16(sb + 16384 + e * 16,
                       Bb + (((size_t)nb * 128 + c * 2 + kc16) * 32 + lane) * 4);
        }
    };

    load_stage(0, 0); cp_commit();
    load_stage(1, 1); cp_commit();

    const int wmb = (wid >> 2) * 4;     // warp A mb base (m offset /16)
    const int wnb = (wid & 3) * 4;      // warp B nb base (n offset /8)

    for (int i = 0; i < 64; i++) {
        if (i + 2 < 64) load_stage((i + 2) % 3, i + 2);
        cp_commit();
        asm volatile("cp.async.wait_group 2;" ::: "memory");
        __syncthreads();

        const uint32_t sA = base + (i % 3) * TSTAGE;
        const uint32_t sB = sA + 16384;
#pragma unroll
        for (int kc16 = 0; kc16 < 2; kc16++) {
            uint32_t b[4][4];
#pragma unroll
            for (int g = 0; g < 4; g++)
                lds128(b[g], sB + (((wnb + g) * 2 + kc16) * 32 + L) * 16);
#pragma unroll
            for (int kh = 0; kh < 2; kh++) {
                uint32_t a[4][4];
                const int kc = kc16 * 2 + kh;
#pragma unroll
                for (int am = 0; am < 4; am++)
                    lds128(a[am], sA + (((wmb + am) * 4 + kc) * 32 + L) * 16);
#pragma unroll
                for (int am = 0; am < 4; am++)
#pragma unroll
                    for (int g = 0; g < 4; g++)
                        mma_tf32(acc[am][g], a[am], b[g][2 * kh], b[g][2 * kh + 1]);
            }
        }
        __syncthreads();
    }

    // epilogue: c0,c1 -> (row, col, col+1); c2,c3 -> (row+8, ...)
#pragma unroll
    for (int am = 0; am < 4; am++) {
        int row = bm + (wid >> 2) * 64 + am * 16 + (L >> 2);
#pragma unroll
        for (int g = 0; g < 4; g++) {
            int col = bn + (wid & 3) * 32 + g * 8 + (L & 3) * 2;
            *(float2*)(C + (size_t)row * Ntot + col) = make_float2(acc[am][g][0], acc[am][g][1]);
            *(float2*)(C + (size_t)(row + 8) * Ntot + col) = make_float2(acc[am][g][2], acc[am][g][3]);
        }
    }
}

// ---------------------------------------------------------------------------
// Fused RoPE + hi/lo split for attention inputs (reads fp32 g_qkv).
// ---------------------------------------------------------------------------
__global__ __launch_bounds__(256) void rope_split(const float* __restrict__ qkv,
                                                  const float* __restrict__ freqs) {
    const int ml = blockIdx.x;            // b*SEQ + l
    const int l = ml & (SEQ - 1);
    const int b = ml >> 11;
    const float* row = qkv + (size_t)ml * NQKV;

#pragma unroll
    for (int it = 0; it < 6; it++) {
        int u = threadIdx.x + it * 256;
        float v0, v1;
        __nv_bfloat16* dst;
        if (u < 1024) {                   // q
            int h = u >> 5, p = u & 31;
            float2 t = *(const float2*)(row + h * 64 + 2 * p);
            float c = freqs[l * 32 + p];
            float s = freqs[SEQ * 32 + l * 32 + p];
            v0 = (t.x * c - t.y * s) * 0.125f;
            v1 = (t.x * s + t.y * c) * 0.125f;
            dst = g_qs + ((size_t)(b * NH + h) * SEQ + l) * 128 + 2 * p;
        } else if (u < 1280) {            // k
            int u2 = u - 1024;
            int kh = u2 >> 5, p = u2 & 31;
            float2 t = *(const float2*)(row + 2048 + kh * 64 + 2 * p);
            float c = freqs[l * 32 + p];
            float s = freqs[SEQ * 32 + l * 32 + p];
            v0 = t.x * c - t.y * s;
            v1 = t.x * s + t.y * c;
            dst = g_ks + ((size_t)(b * NKV + kh) * SEQ + l) * 128 + 2 * p;
        } else {                          // v
            int u2 = u - 1280;
            int kh = u2 >> 5, p = u2 & 31;
            float2 t = *(const float2*)(row + 2560 + kh * 64 + 2 * p);
            v0 = t.x; v1 = t.y;
            dst = g_vs + ((size_t)(b * NKV + kh) * SEQ + l) * 128 + 2 * p;
        }
        __nv_bfloat16 h0 = __float2bfloat16(v0);
        __nv_bfloat16 h1 = __float2bfloat16(v1);
        dst[0] = h0;
        dst[1] = h1;
        dst[64] = __float2bfloat16(v0 - __bfloat162float(h0));
        dst[65] = __float2bfloat16(v1 - __bfloat162float(h1));
    }
}

// ---------------------------------------------------------------------------
// Tensor-core causal flash attention, bf16 hi/lo splits both sides.
// Writes fp32 g_attn [4096][2048] row-major.
// ---------------------------------------------------------------------------
constexpr int AT_STR = 144;
constexpr int AT_ARR = 64 * AT_STR;
constexpr int AT_SMEM = 6 * AT_ARR;                // 55296
constexpr float LOG2E = 1.4426950408889634f;

__global__ __launch_bounds__(128, 2)
void flash_attn_mma(const __nv_bfloat16* __restrict__ Qs,
                    const __nv_bfloat16* __restrict__ Ks,
                    const __nv_bfloat16* __restrict__ Vs) {
    extern __shared__ __align__(128) char fsm[];
    const uint32_t sQh = smem_u32(fsm);
    const uint32_t sQl = sQh + AT_ARR;
    const uint32_t sKh = sQh + 2 * AT_ARR;
    const uint32_t sKl = sQh + 3 * AT_ARR;
    const uint32_t sVh = sQh + 4 * AT_ARR;
    const uint32_t sVl = sQh + 5 * AT_ARR;

    const int tid = threadIdx.x;
    const int wid = tid >> 5;
    const int L = tid & 31;
    const int wm = wid * 16;
    const uint32_t lrow = L & 15;
    const uint32_t lcol16 = (L >> 4) * 16;

    const int m0 = blockIdx.x * 64;
    const int h = blockIdx.y;
    const int b = blockIdx.z;
    const int kvh = h >> 2;

    const __nv_bfloat16* qsrc = Qs + ((size_t)(b * NH + h) * SEQ + m0) * 128;
#pragma unroll
    for (int u = 0; u < 8; u++) {
        int e = tid + u * 128;
        int row = e >> 4, ch = e & 15;
        uint32_t dst = (ch < 8) ? (sQh + row * AT_STR + ch * 16)
                                : (sQl + row * AT_STR + (ch - 8) * 16);
        cp_async16(dst, qsrc + (size_t)row * 128 + ch * 8);
    }
    cp_commit();
    asm volatile("cp.async.wait_group 0;" ::: "memory");
    __syncthreads();

    uint32_t qh[4][4], ql[4][4];
#pragma unroll
    for (int kg = 0; kg < 4; kg++) {
        ldm_x4(qh[kg], sQh + (wm + lrow) * AT_STR + kg * 32 + lcol16);
        ldm_x4(ql[kg], sQl + (wm + lrow) * AT_STR + kg * 32 + lcol16);
    }

    float O[8][4];
#pragma unroll
    for (int i = 0; i < 8; i++)
#pragma unroll
        for (int j = 0; j < 4; j++) O[i][j] = 0.f;
    float mr0 = -1e30f, mr1 = -1e30f, lr0 = 0.f, lr1 = 0.f;

    const __nv_bfloat16* ksrc = Ks + ((size_t)(b * NKV + kvh) * SEQ) * 128;
    const __nv_bfloat16* vsrc = Vs + ((size_t)(b * NKV + kvh) * SEQ) * 128;

    const int nT = m0 / 64 + 1;
    for (int t = 0; t < nT; t++) {
        const int n0 = t * 64;
        __syncthreads();
#pragma unroll
        for (int u = 0; u < 8; u++) {
            int e = tid + u * 128;
            int row = e >> 4, ch = e & 15;
            uint32_t kd = (ch < 8) ? (sKh + row * AT_STR + ch * 16)
                                   : (sKl + row * AT_STR + (ch - 8) * 16);
            uint32_t vd = (ch < 8) ? (sVh + row * AT_STR + ch * 16)
                                   : (sVl + row * AT_STR + (ch - 8) * 16);
            cp_async16(kd, ksrc + (size_t)(n0 + row) * 128 + ch * 8);
            cp_async16(vd, vsrc + (size_t)(n0 + row) * 128 + ch * 8);
        }
        cp_commit();
        asm volatile("cp.async.wait_group 0;" ::: "memory");
        __syncthreads();

        float S[8][4];
#pragma unroll
        for (int i = 0; i < 8; i++)
#pragma unroll
            for (int j = 0; j < 4; j++) S[i][j] = 0.f;

#pragma unroll
        for (int kg = 0; kg < 4; kg++) {
            uint32_t kfh[4][4], kfl[4][4];
#pragma unroll
            for (int nn = 0; nn < 4; nn++) {
                ldm_x4(kfh[nn], sKh + (nn * 16 + lrow) * AT_STR + kg * 32 + lcol16);
                ldm_x4(kfl[nn], sKl + (nn * 16 + lrow) * AT_STR + kg * 32 + lcol16);
            }
#pragma unroll
            for (int ng = 0; ng < 8; ng++) {
                int nn = ng >> 1, e = ng & 1;
                mma_16816(S[ng], qh[kg], kfh[nn][e], kfh[nn][2 + e]);
                mma_16816(S[ng], qh[kg], kfl[nn][e], kfl[nn][2 + e]);
                mma_16816(S[ng], ql[kg], kfh[nn][e], kfh[nn][2 + e]);
            }
        }

        const int r0 = wm + (L >> 2);
        const int r1 = r0 + 8;
        if (t == nT - 1) {
#pragma unroll
            for (int ng = 0; ng < 8; ng++) {
                int c0 = ng * 8 + (L & 3) * 2;
                if (c0 > r0)     S[ng][0] = -1e30f;
                if (c0 + 1 > r0) S[ng][1] = -1e30f;
                if (c0 > r1)     S[ng][2] = -1e30f;
                if (c0 + 1 > r1) S[ng][3] = -1e30f;
            }
        }

        float t0 = -1e30f, t1 = -1e30f;
#pragma unroll
        for (int ng = 0; ng < 8; ng++) {
            t0 = fmaxf(t0, fmaxf(S[ng][0], S[ng][1]));
            t1 = fmaxf(t1, fmaxf(S[ng][2], S[ng][3]));
        }
        t0 = fmaxf(t0, __shfl_xor_sync(0xffffffffu, t0, 1));
        t0 = fmaxf(t0, __shfl_xor_sync(0xffffffffu, t0, 2));
        t1 = fmaxf(t1, __shfl_xor_sync(0xffffffffu, t1, 1));
        t1 = fmaxf(t1, __shfl_xor_sync(0xffffffffu, t1, 2));

        float mn0 = fmaxf(mr0, t0), mn1 = fmaxf(mr1, t1);
        float corr0 = ex2f((mr0 - mn0) * LOG2E);
        float corr1 = ex2f((mr1 - mn1) * LOG2E);
        lr0 *= corr0; lr1 *= corr1;
#pragma unroll
        for (int ng = 0; ng < 8; ng++) {
            O[ng][0] *= corr0; O[ng][1] *= corr0;
            O[ng][2] *= corr1; O[ng][3] *= corr1;
        }
        mr0 = mn0; mr1 = mn1;
        const float mb0 = mn0 * LOG2E, mb1 = mn1 * LOG2E;

        uint32_t pah[4][4], pal[4][4];
        float s0 = 0.f, s1 = 0.f;
#pragma unroll
        for (int kg = 0; kg < 4; kg++) {
            float p[8];
#pragma unroll
            for (int e = 0; e < 2; e++) {
                const int g = 2 * kg + e;
                p[4 * e + 0] = ex2f(fmaf(S[g][0], LOG2E, -mb0));
                p[4 * e + 1] = ex2f(fmaf(S[g][1], LOG2E, -mb0));
                p[4 * e + 2] = ex2f(fmaf(S[g][2], LOG2E, -mb1));
                p[4 * e + 3] = ex2f(fmaf(S[g][3], LOG2E, -mb1));
                s0 += p[4 * e] + p[4 * e + 1];
                s1 += p[4 * e + 2] + p[4 * e + 3];
            }
            pah[kg][0] = prmt_hi(p[0], p[1]);
            pah[kg][1] = prmt_hi(p[2], p[3]);
            pah[kg][2] = prmt_hi(p[4], p[5]);
            pah[kg][3] = prmt_hi(p[6], p[7]);
            pal[kg][0] = pack_bf16(p[0] - trunc_bf(p[0]), p[1] - trunc_bf(p[1]));
            pal[kg][1] = pack_bf16(p[2] - trunc_bf(p[2]), p[3] - trunc_bf(p[3]));
            pal[kg][2] = pack_bf16(p[4] - trunc_bf(p[4]), p[5] - trunc_bf(p[5]));
            pal[kg][3] = pack_bf16(p[6] - trunc_bf(p[6]), p[7] - trunc_bf(p[7]));
        }
        s0 += __shfl_xor_sync(0xffffffffu, s0, 1);
        s0 += __shfl_xor_sync(0xffffffffu, s0, 2);
        s1 += __shfl_xor_sync(0xffffffffu, s1, 1);
        s1 += __shfl_xor_sync(0xffffffffu, s1, 2);
        lr0 += s0; lr1 += s1;

#pragma unroll
        for (int kg = 0; kg < 4; kg++) {
            uint32_t vfh[4][4], vfl[4][4];
#pragma unroll
            for (int cp = 0; cp < 4; cp++) {
                ldm_x4_t(vfh[cp], sVh + (kg * 16 + lrow) * AT_STR + cp * 32 + lcol16);
                ldm_x4_t(vfl[cp], sVl + (kg * 16 + lrow) * AT_STR + cp * 32 + lcol16);
            }
#pragma unroll
            for (int cp = 0; cp < 4; cp++) {
#pragma unroll
                for (int e = 0; e < 2; e++) {
                    const int ng = 2 * cp + e;
                    mma_16816(O[ng], pah[kg], vfh[cp][2 * e], vfh[cp][2 * e + 1]);
                    mma_16816(O[ng], pah[kg], vfl[cp][2 * e], vfl[cp][2 * e + 1]);
                    mma_16816(O[ng], pal[kg], vfh[cp][2 * e], vfh[cp][2 * e + 1]);
                }
            }
        }
    }

    const float inv0 = 1.f / lr0;
    const float inv1 = 1.f / lr1;
    const int r0 = wm + (L >> 2);
    float* o0 = g_attn + (size_t)(b * SEQ + m0 + r0) * 2048 + h * 64 + (L & 3) * 2;
    float* o1 = g_attn + (size_t)(b * SEQ + m0 + r0 + 8) * 2048 + h * 64 + (L & 3) * 2;
#pragma unroll
    for (int ng = 0; ng < 8; ng++) {
        *(float2*)(o0 + ng * 8) = make_float2(O[ng][0] * inv0, O[ng][1] * inv0);
        *(float2*)(o1 + ng * 8) = make_float2(O[ng][2] * inv1, O[ng][3] * inv1);
    }
}

// ---------------------------------------------------------------------------
extern "C" void kernel_launch(void* const* d_in, const int* in_sizes, int n_in,
                              void* d_out, int out_size) {
    const float* x     = (const float*)d_in[0];
    const float* freqs = (const float*)d_in[1];
    const float* wq    = (const float*)d_in[2];
    const float* wk    = (const float*)d_in[3];
    const float* wv    = (const float*)d_in[4];
    const float* wo    = (const float*)d_in[5];
    float* out = (float*)d_out;

    uint32_t *xt, *wqkvt, *wot, *at;
    float *qkv, *attn;
    __nv_bfloat16 *qs, *ks, *vs;
    cudaGetSymbolAddress((void**)&xt, g_xt);
    cudaGetSymbolAddress((void**)&wqkvt, g_wqkvt);
    cudaGetSymbolAddress((void**)&wot, g_wot);
    cudaGetSymbolAddress((void**)&at, g_at);
    cudaGetSymbolAddress((void**)&qkv, g_qkv);
    cudaGetSymbolAddress((void**)&attn, g_attn);
    cudaGetSymbolAddress((void**)&qs, g_qs);
    cudaGetSymbolAddress((void**)&ks, g_ks);
    cudaGetSymbolAddress((void**)&vs, g_vs);

    static bool attr_done = false;
    if (!attr_done) {
        cudaFuncSetAttribute(gemm_tf32, cudaFuncAttributeMaxDynamicSharedMemorySize, GSMEM);
        cudaFuncSetAttribute(flash_attn_mma, cudaFuncAttributeMaxDynamicSharedMemorySize, AT_SMEM);
        attr_done = true;
    }

    // 1-2) pack x (two halves, keeps QKV gemm at profiled launch slot #5)
    pack_a<<<4096, 256>>>(x, xt, 0, 128);
    pack_a<<<4096, 256>>>(x, xt, 128, 128);
    // 3) pack merged qkv weights, 4) pack wo
    pack_b_qkv<<<(NQKV / 8 * 4096) / 256, 256>>>(wq, wk, wv, wqkvt, NQKV / 8 * 4096);
    pack_b<<<(DIMM / 8 * 4096) / 256, 256>>>(wo, wot, DIMM / 8 * 4096);

    // 5) fused QKV projection: [4096,3072]
    gemm_tf32<<<dim3(NQKV / 128, MROWS / 128), 256, GSMEM>>>(xt, wqkvt, qkv, NQKV);

    // 6) RoPE + hi/lo split for attention inputs
    rope_split<<<MROWS, 256>>>(qkv, freqs);

    // 7) tensor-core attention -> fp32 g_attn
    flash_attn_mma<<<dim3(SEQ / 64, NH, BB), 128, AT_SMEM>>>(qs, ks, vs);

    // 8) pack attn output for O projection
    pack_a<<<8192, 256>>>(attn, at, 0, 256);

    // 9) O projection
    gemm_tf32<<<dim3(DIMM / 128, MROWS / 128), 256, GSMEM>>>(at, wot, out, DIMM);
}

// round 8
// speedup vs baseline: 2.2969x; 1.3261x over previous
#include <cuda_runtime.h>
#include <cuda_bf16.h>
#include <cuda_fp16.h>
#include <cstdint>
#include <cstddef>

// Problem constants
constexpr int BB   = 2;
constexpr int SEQ  = 2048;
constexpr int DIMM = 2048;
constexpr int NH   = 32;
constexpr int NKV  = 8;
constexpr int HDIM = 64;
constexpr int MROWS = BB * SEQ;                    // 4096
constexpr int NQKV  = NH * HDIM + 2 * NKV * HDIM;  // 3072

// ---------------------------------------------------------------------------
// Scratch (device globals; allocation-free rule)
// fp16 fragment-packed operands (m16n8k16):
//  A-pack: [mb=row/16][kc16=k/16 (128)][lane][4 half2 words] = 16384 words/mb
//  B-pack: [nb=n/8][kc32=k/32 (64)][lane][4 half2 words]     = 8192 words/nb
// ---------------------------------------------------------------------------
__device__ uint32_t g_xt[MROWS * DIMM / 2];         // packed x           16 MB
__device__ uint32_t g_wqkvt[NQKV * DIMM / 2];       // packed wq|wk|wv    12 MB
__device__ uint32_t g_wot[DIMM * DIMM / 2];         // packed wo           8 MB
__device__ uint32_t g_at[MROWS * DIMM / 2];         // packed attn out    16 MB
__device__ float g_qkv[MROWS * NQKV];               // q|k|v fp32         48 MB
__device__ float g_attn[MROWS * NH * HDIM];         // attn out fp32      32 MB
// attention inputs, bf16 [hi(64) | lo(64)] per row
__device__ __nv_bfloat16 g_qs[BB * NH * SEQ * 128];   // 32 MB (q prescaled by 1/8)
__device__ __nv_bfloat16 g_ks[BB * NKV * SEQ * 128];  // 8 MB
__device__ __nv_bfloat16 g_vs[BB * NKV * SEQ * 128];  // 8 MB

// ---------------------------------------------------------------------------
// Helpers
// ---------------------------------------------------------------------------
__device__ __forceinline__ uint32_t smem_u32(const void* p) {
    uint32_t a;
    asm("{ .reg .u64 t; cvta.to.shared.u64 t, %1; cvt.u32.u64 %0, t; }" : "=r"(a) : "l"(p));
    return a;
}
__device__ __forceinline__ void cp_async16(uint32_t dst, const void* src) {
    asm volatile("cp.async.cg.shared.global [%0], [%1], 16;" :: "r"(dst), "l"(src));
}
__device__ __forceinline__ void cp_commit() { asm volatile("cp.async.commit_group;" ::: "memory"); }

__device__ __forceinline__ void lds128(uint32_t* r, uint32_t addr) {
    asm volatile("ld.shared.v4.b32 {%0,%1,%2,%3}, [%4];"
        : "=r"(r[0]), "=r"(r[1]), "=r"(r[2]), "=r"(r[3]) : "r"(addr));
}
__device__ __forceinline__ void ldm_x4(uint32_t* r, uint32_t addr) {
    asm volatile("ldmatrix.sync.aligned.m8n8.x4.shared.b16 {%0,%1,%2,%3}, [%4];"
        : "=r"(r[0]), "=r"(r[1]), "=r"(r[2]), "=r"(r[3]) : "r"(addr));
}
__device__ __forceinline__ void ldm_x4_t(uint32_t* r, uint32_t addr) {
    asm volatile("ldmatrix.sync.aligned.m8n8.x4.trans.shared.b16 {%0,%1,%2,%3}, [%4];"
        : "=r"(r[0]), "=r"(r[1]), "=r"(r[2]), "=r"(r[3]) : "r"(addr));
}
__device__ __forceinline__ void mma_16816(float* d, const uint32_t* a, uint32_t b0, uint32_t b1) {
    asm volatile("mma.sync.aligned.m16n8k16.row.col.f32.bf16.bf16.f32 "
        "{%0,%1,%2,%3}, {%4,%5,%6,%7}, {%8,%9}, {%0,%1,%2,%3};"
        : "+f"(d[0]), "+f"(d[1]), "+f"(d[2]), "+f"(d[3])
        : "r"(a[0]), "r"(a[1]), "r"(a[2]), "r"(a[3]), "r"(b0), "r"(b1));
}
__device__ __forceinline__ void mma_f16(float* d, const uint32_t* a, uint32_t b0, uint32_t b1) {
    asm volatile("mma.sync.aligned.m16n8k16.row.col.f32.f16.f16.f32 "
        "{%0,%1,%2,%3}, {%4,%5,%6,%7}, {%8,%9}, {%0,%1,%2,%3};"
        : "+f"(d[0]), "+f"(d[1]), "+f"(d[2]), "+f"(d[3])
        : "r"(a[0]), "r"(a[1]), "r"(a[2]), "r"(a[3]), "r"(b0), "r"(b1));
}
__device__ __forceinline__ uint32_t f2h2(float lo, float hi) {
    __half2 h = __floats2half2_rn(lo, hi);
    return *(uint32_t*)&h;
}
__device__ __forceinline__ float ex2f(float x) {
    float r;
    asm("ex2.approx.f32 %0, %1;" : "=f"(r) : "f"(x));
    return r;
}
__device__ __forceinline__ uint32_t prmt_hi(float a, float b) {
    uint32_t r;
    asm("prmt.b32 %0, %1, %2, 0x7632;" : "=r"(r) : "r"(__float_as_uint(a)), "r"(__float_as_uint(b)));
    return r;
}
__device__ __forceinline__ uint32_t pack_bf16(float lo, float hi) {
    uint32_t r;
    asm("cvt.rn.bf16x2.f32 %0, %2, %1;" : "=r"(r) : "f"(lo), "f"(hi));
    return r;
}
__device__ __forceinline__ float trunc_bf(float x) {
    return __uint_as_float(__float_as_uint(x) & 0xffff0000u);
}

// ---------------------------------------------------------------------------
// pack_a: fp32 [rows][2048] -> fp16 A-fragment pack (m16n8k16).
// idx per (mb, kc16, lane): a0={r,c2}, a1={r+8,c2}, a2={r,c2+8}, a3={r+8,c2+8}
// ---------------------------------------------------------------------------
__global__ __launch_bounds__(256) void pack_a(const float* __restrict__ src,
                                              uint32_t* __restrict__ dst,
                                              int mb0, int nmb) {
    int idx = blockIdx.x * 256 + threadIdx.x;
    if (idx >= nmb * 4096) return;
    int lane = idx & 31;
    int kc16 = (idx >> 5) & 127;
    int mb = (idx >> 12) + mb0;
    int r = lane >> 2;
    int c2 = kc16 * 16 + (lane & 3) * 2;
    const float* s = src + (size_t)mb * 16 * 2048;
    uint4 o;
    o.x = f2h2(s[(size_t)r * 2048 + c2],        s[(size_t)r * 2048 + c2 + 1]);
    o.y = f2h2(s[(size_t)(r + 8) * 2048 + c2],  s[(size_t)(r + 8) * 2048 + c2 + 1]);
    o.z = f2h2(s[(size_t)r * 2048 + c2 + 8],    s[(size_t)r * 2048 + c2 + 9]);
    o.w = f2h2(s[(size_t)(r + 8) * 2048 + c2 + 8], s[(size_t)(r + 8) * 2048 + c2 + 9]);
    ((uint4*)dst)[(size_t)mb * 4096 + (idx & 4095)] = o;
}

// ---------------------------------------------------------------------------
// pack_b: weights [N][2048] -> fp16 B-fragment pack.
// idx per (nb, kc32, lane): words = {b0,b1 of kc16=0, b0,b1 of kc16=1}
// ---------------------------------------------------------------------------
__global__ __launch_bounds__(256) void pack_b(const float* __restrict__ src,
                                              uint32_t* __restrict__ dst, int total) {
    int idx = blockIdx.x * 256 + threadIdx.x;
    if (idx >= total) return;
    int lane = idx & 31;
    int kc32 = (idx >> 5) & 63;
    int nb = idx >> 11;
    int n = nb * 8 + (lane >> 2);
    int k2 = kc32 * 32 + (lane & 3) * 2;
    const float* s = src + (size_t)n * 2048 + k2;
    uint4 o;
    o.x = f2h2(s[0],  s[1]);
    o.y = f2h2(s[8],  s[9]);
    o.z = f2h2(s[16], s[17]);
    o.w = f2h2(s[24], s[25]);
    ((uint4*)dst)[idx] = o;
}

__global__ __launch_bounds__(256) void pack_b_qkv(const float* __restrict__ wq,
                                                  const float* __restrict__ wk,
                                                  const float* __restrict__ wv,
                                                  uint32_t* __restrict__ dst, int total) {
    int idx = blockIdx.x * 256 + threadIdx.x;
    if (idx >= total) return;
    int lane = idx & 31;
    int kc32 = (idx >> 5) & 63;
    int nb = idx >> 11;
    int n = nb * 8 + (lane >> 2);
    int k2 = kc32 * 32 + (lane & 3) * 2;
    const float* s;
    if (n < 2048)      s = wq + (size_t)n * 2048 + k2;
    else if (n < 2560) s = wk + (size_t)(n - 2048) * 2048 + k2;
    else               s = wv + (size_t)(n - 2560) * 2048 + k2;
    uint4 o;
    o.x = f2h2(s[0],  s[1]);
    o.y = f2h2(s[8],  s[9]);
    o.z = f2h2(s[16], s[17]);
    o.w = f2h2(s[24], s[25]);
    ((uint4*)dst)[idx] = o;
}

// ---------------------------------------------------------------------------
// fp16 GEMM: C[M,N] = A[M,2048] * B[N,2048]^T, operands fragment-packed.
// CTA 128x128, 256 thr, warps 2x4 (warp tile 64x32), K-chunk 32,
// 4-stage cp.async pipeline (16KB/stage), 2 CTAs/SM.
// ---------------------------------------------------------------------------
constexpr int FSTAGE = 16384;
constexpr int GSMEM  = 4 * FSTAGE;                 // 65536

__global__ __launch_bounds__(256, 2)
void gemm_f16(const uint32_t* __restrict__ A, const uint32_t* __restrict__ B,
              float* __restrict__ C, int Ntot) {
    extern __shared__ __align__(128) char dsm[];
    const int tid = threadIdx.x;
    const int wid = tid >> 5;
    const int L = tid & 31;
    const uint32_t base = smem_u32(dsm);
    const int bm = blockIdx.y * 128;
    const int bn = blockIdx.x * 128;
    const uint32_t* Ab = A + (size_t)(bm >> 4) * 16384;  // words per mb block
    const uint32_t* Bb = B + (size_t)(bn >> 3) * 8192;   // words per nb block

    float acc[4][4][4];
#pragma unroll
    for (int i = 0; i < 4; i++)
#pragma unroll
        for (int j = 0; j < 4; j++)
#pragma unroll
            for (int q = 0; q < 4; q++) acc[i][j][q] = 0.f;

    auto load_stage = [&](int s, int c) {        // K-chunk c: k = c*32..+31
        const uint32_t sb = base + s * FSTAGE;
#pragma unroll
        for (int u = 0; u < 2; u++) {            // A: 512 x 16B (8 mb x 2 kc16)
            int e = tid + u * 256;
            int lane = e & 31, kcl = (e >> 5) & 1, mb = e >> 6;
            cp_async16(sb + e * 16,
                       Ab + (((size_t)mb * 128 + c * 2 + kcl) * 32 + lane) * 4);
        }
#pragma unroll
        for (int u = 0; u < 2; u++) {            // B: 512 x 16B (16 nb)
            int e = tid + u * 256;
            int lane = e & 31, nb = e >> 5;
            cp_async16(sb + 8192 + e * 16,
                       Bb + (((size_t)nb * 64 + c) * 32 + lane) * 4);
        }
    };

    load_stage(0, 0); cp_commit();
    load_stage(1, 1); cp_commit();
    load_stage(2, 2); cp_commit();

    const int wmb = (wid >> 2) * 4;     // warp A mb base (m/16)
    const int wnb = (wid & 3) * 4;      // warp B nb base (n/8)

    for (int i = 0; i < 64; i++) {
        if (i + 3 < 64) load_stage((i + 3) & 3, i + 3);
        cp_commit();
        asm volatile("cp.async.wait_group 3;" ::: "memory");
        __syncthreads();

        const uint32_t sA = base + (i & 3) * FSTAGE;
        const uint32_t sB = sA + 8192;
        uint32_t b[4][4];
#pragma unroll
        for (int g = 0; g < 4; g++)
            lds128(b[g], sB + (((wnb + g) * 32) + L) * 16);
#pragma unroll
        for (int kcl = 0; kcl < 2; kcl++) {
            uint32_t a[4][4];
#pragma unroll
            for (int am = 0; am < 4; am++)
                lds128(a[am], sA + (((wmb + am) * 2 + kcl) * 32 + L) * 16);
#pragma unroll
            for (int am = 0; am < 4; am++)
#pragma unroll
                for (int g = 0; g < 4; g++)
                    mma_f16(acc[am][g], a[am], b[g][2 * kcl], b[g][2 * kcl + 1]);
        }
        __syncthreads();
    }

    // epilogue: c0,c1 -> (row, col, col+1); c2,c3 -> (row+8, ...)
#pragma unroll
    for (int am = 0; am < 4; am++) {
        int row = bm + (wid >> 2) * 64 + am * 16 + (L >> 2);
#pragma unroll
        for (int g = 0; g < 4; g++) {
            int col = bn + (wid & 3) * 32 + g * 8 + (L & 3) * 2;
            *(float2*)(C + (size_t)row * Ntot + col) = make_float2(acc[am][g][0], acc[am][g][1]);
            *(float2*)(C + (size_t)(row + 8) * Ntot + col) = make_float2(acc[am][g][2], acc[am][g][3]);
        }
    }
}

// ---------------------------------------------------------------------------
// Fused RoPE + hi/lo split for attention inputs (reads fp32 g_qkv).
// ---------------------------------------------------------------------------
__global__ __launch_bounds__(256) void rope_split(const float* __restrict__ qkv,
                                                  const float* __restrict__ freqs) {
    const int ml = blockIdx.x;            // b*SEQ + l
    const int l = ml & (SEQ - 1);
    const int b = ml >> 11;
    const float* row = qkv + (size_t)ml * NQKV;

#pragma unroll
    for (int it = 0; it < 6; it++) {
        int u = threadIdx.x + it * 256;
        float v0, v1;
        __nv_bfloat16* dst;
        if (u < 1024) {                   // q
            int h = u >> 5, p = u & 31;
            float2 t = *(const float2*)(row + h * 64 + 2 * p);
            float c = freqs[l * 32 + p];
            float s = freqs[SEQ * 32 + l * 32 + p];
            v0 = (t.x * c - t.y * s) * 0.125f;
            v1 = (t.x * s + t.y * c) * 0.125f;
            dst = g_qs + ((size_t)(b * NH + h) * SEQ + l) * 128 + 2 * p;
        } else if (u < 1280) {            // k
            int u2 = u - 1024;
            int kh = u2 >> 5, p = u2 & 31;
            float2 t = *(const float2*)(row + 2048 + kh * 64 + 2 * p);
            float c = freqs[l * 32 + p];
            float s = freqs[SEQ * 32 + l * 32 + p];
            v0 = t.x * c - t.y * s;
            v1 = t.x * s + t.y * c;
            dst = g_ks + ((size_t)(b * NKV + kh) * SEQ + l) * 128 + 2 * p;
        } else {                          // v
            int u2 = u - 1280;
            int kh = u2 >> 5, p = u2 & 31;
            float2 t = *(const float2*)(row + 2560 + kh * 64 + 2 * p);
            v0 = t.x; v1 = t.y;
            dst = g_vs + ((size_t)(b * NKV + kh) * SEQ + l) * 128 + 2 * p;
        }
        __nv_bfloat16 h0 = __float2bfloat16(v0);
        __nv_bfloat16 h1 = __float2bfloat16(v1);
        dst[0] = h0;
        dst[1] = h1;
        dst[64] = __float2bfloat16(v0 - __bfloat162float(h0));
        dst[65] = __float2bfloat16(v1 - __bfloat162float(h1));
    }
}

// ---------------------------------------------------------------------------
// Tensor-core causal flash attention, bf16 hi/lo splits both sides.
// Writes fp32 g_attn [4096][2048] row-major.
// ---------------------------------------------------------------------------
constexpr int AT_STR = 144;
constexpr int AT_ARR = 64 * AT_STR;
constexpr int AT_SMEM = 6 * AT_ARR;                // 55296
constexpr float LOG2E = 1.4426950408889634f;

__global__ __launch_bounds__(128, 2)
void flash_attn_mma(const __nv_bfloat16* __restrict__ Qs,
                    const __nv_bfloat16* __restrict__ Ks,
                    const __nv_bfloat16* __restrict__ Vs) {
    extern __shared__ __align__(128) char fsm[];
    const uint32_t sQh = smem_u32(fsm);
    const uint32_t sQl = sQh + AT_ARR;
    const uint32_t sKh = sQh + 2 * AT_ARR;
    const uint32_t sKl = sQh + 3 * AT_ARR;
    const uint32_t sVh = sQh + 4 * AT_ARR;
    const uint32_t sVl = sQh + 5 * AT_ARR;

    const int tid = threadIdx.x;
    const int wid = tid >> 5;
    const int L = tid & 31;
    const int wm = wid * 16;
    const uint32_t lrow = L & 15;
    const uint32_t lcol16 = (L >> 4) * 16;

    const int m0 = blockIdx.x * 64;
    const int h = blockIdx.y;
    const int b = blockIdx.z;
    const int kvh = h >> 2;

    const __nv_bfloat16* qsrc = Qs + ((size_t)(b * NH + h) * SEQ + m0) * 128;
#pragma unroll
    for (int u = 0; u < 8; u++) {
        int e = tid + u * 128;
        int row = e >> 4, ch = e & 15;
        uint32_t dst = (ch < 8) ? (sQh + row * AT_STR + ch * 16)
                                : (sQl + row * AT_STR + (ch - 8) * 16);
        cp_async16(dst, qsrc + (size_t)row * 128 + ch * 8);
    }
    cp_commit();
    asm volatile("cp.async.wait_group 0;" ::: "memory");
    __syncthreads();

    uint32_t qh[4][4], ql[4][4];
#pragma unroll
    for (int kg = 0; kg < 4; kg++) {
        ldm_x4(qh[kg], sQh + (wm + lrow) * AT_STR + kg * 32 + lcol16);
        ldm_x4(ql[kg], sQl + (wm + lrow) * AT_STR + kg * 32 + lcol16);
    }

    float O[8][4];
#pragma unroll
    for (int i = 0; i < 8; i++)
#pragma unroll
        for (int j = 0; j < 4; j++) O[i][j] = 0.f;
    float mr0 = -1e30f, mr1 = -1e30f, lr0 = 0.f, lr1 = 0.f;

    const __nv_bfloat16* ksrc = Ks + ((size_t)(b * NKV + kvh) * SEQ) * 128;
    const __nv_bfloat16* vsrc = Vs + ((size_t)(b * NKV + kvh) * SEQ) * 128;

    const int nT = m0 / 64 + 1;
    for (int t = 0; t < nT; t++) {
        const int n0 = t * 64;
        __syncthreads();
#pragma unroll
        for (int u = 0; u < 8; u++) {
            int e = tid + u * 128;
            int row = e >> 4, ch = e & 15;
            uint32_t kd = (ch < 8) ? (sKh + row * AT_STR + ch * 16)
                                   : (sKl + row * AT_STR + (ch - 8) * 16);
            uint32_t vd = (ch < 8) ? (sVh + row * AT_STR + ch * 16)
                                   : (sVl + row * AT_STR + (ch - 8) * 16);
            cp_async16(kd, ksrc + (size_t)(n0 + row) * 128 + ch * 8);
            cp_async16(vd, vsrc + (size_t)(n0 + row) * 128 + ch * 8);
        }
        cp_commit();
        asm volatile("cp.async.wait_group 0;" ::: "memory");
        __syncthreads();

        float S[8][4];
#pragma unroll
        for (int i = 0; i < 8; i++)
#pragma unroll
            for (int j = 0; j < 4; j++) S[i][j] = 0.f;

#pragma unroll
        for (int kg = 0; kg < 4; kg++) {
            uint32_t kfh[4][4], kfl[4][4];
#pragma unroll
            for (int nn = 0; nn < 4; nn++) {
                ldm_x4(kfh[nn], sKh + (nn * 16 + lrow) * AT_STR + kg * 32 + lcol16);
                ldm_x4(kfl[nn], sKl + (nn * 16 + lrow) * AT_STR + kg * 32 + lcol16);
            }
#pragma unroll
            for (int ng = 0; ng < 8; ng++) {
                int nn = ng >> 1, e = ng & 1;
                mma_16816(S[ng], qh[kg], kfh[nn][e], kfh[nn][2 + e]);
                mma_16816(S[ng], qh[kg], kfl[nn][e], kfl[nn][2 + e]);
                mma_16816(S[ng], ql[kg], kfh[nn][e], kfh[nn][2 + e]);
            }
        }

        const int r0 = wm + (L >> 2);
        const int r1 = r0 + 8;
        if (t == nT - 1) {
#pragma unroll
            for (int ng = 0; ng < 8; ng++) {
                int c0 = ng * 8 + (L & 3) * 2;
                if (c0 > r0)     S[ng][0] = -1e30f;
                if (c0 + 1 > r0) S[ng][1] = -1e30f;
                if (c0 > r1)     S[ng][2] = -1e30f;
                if (c0 + 1 > r1) S[ng][3] = -1e30f;
            }
        }

        float t0 = -1e30f, t1 = -1e30f;
#pragma unroll
        for (int ng = 0; ng < 8; ng++) {
            t0 = fmaxf(t0, fmaxf(S[ng][0], S[ng][1]));
            t1 = fmaxf(t1, fmaxf(S[ng][2], S[ng][3]));
        }
        t0 = fmaxf(t0, __shfl_xor_sync(0xffffffffu, t0, 1));
        t0 = fmaxf(t0, __shfl_xor_sync(0xffffffffu, t0, 2));
        t1 = fmaxf(t1, __shfl_xor_sync(0xffffffffu, t1, 1));
        t1 = fmaxf(t1, __shfl_xor_sync(0xffffffffu, t1, 2));

        float mn0 = fmaxf(mr0, t0), mn1 = fmaxf(mr1, t1);
        float corr0 = ex2f((mr0 - mn0) * LOG2E);
        float corr1 = ex2f((mr1 - mn1) * LOG2E);
        lr0 *= corr0; lr1 *= corr1;
#pragma unroll
        for (int ng = 0; ng < 8; ng++) {
            O[ng][0] *= corr0; O[ng][1] *= corr0;
            O[ng][2] *= corr1; O[ng][3] *= corr1;
        }
        mr0 = mn0; mr1 = mn1;
        const float mb0 = mn0 * LOG2E, mb1 = mn1 * LOG2E;

        uint32_t pah[4][4], pal[4][4];
        float s0 = 0.f, s1 = 0.f;
#pragma unroll
        for (int kg = 0; kg < 4; kg++) {
            float p[8];
#pragma unroll
            for (int e = 0; e < 2; e++) {
                const int g = 2 * kg + e;
                p[4 * e + 0] = ex2f(fmaf(S[g][0], LOG2E, -mb0));
                p[4 * e + 1] = ex2f(fmaf(S[g][1], LOG2E, -mb0));
                p[4 * e + 2] = ex2f(fmaf(S[g][2], LOG2E, -mb1));
                p[4 * e + 3] = ex2f(fmaf(S[g][3], LOG2E, -mb1));
                s0 += p[4 * e] + p[4 * e + 1];
                s1 += p[4 * e + 2] + p[4 * e + 3];
            }
            pah[kg][0] = prmt_hi(p[0], p[1]);
            pah[kg][1] = prmt_hi(p[2], p[3]);
            pah[kg][2] = prmt_hi(p[4], p[5]);
            pah[kg][3] = prmt_hi(p[6], p[7]);
            pal[kg][0] = pack_bf16(p[0] - trunc_bf(p[0]), p[1] - trunc_bf(p[1]));
            pal[kg][1] = pack_bf16(p[2] - trunc_bf(p[2]), p[3] - trunc_bf(p[3]));
            pal[kg][2] = pack_bf16(p[4] - trunc_bf(p[4]), p[5] - trunc_bf(p[5]));
            pal[kg][3] = pack_bf16(p[6] - trunc_bf(p[6]), p[7] - trunc_bf(p[7]));
        }
        s0 += __shfl_xor_sync(0xffffffffu, s0, 1);
        s0 += __shfl_xor_sync(0xffffffffu, s0, 2);
        s1 += __shfl_xor_sync(0xffffffffu, s1, 1);
        s1 += __shfl_xor_sync(0xffffffffu, s1, 2);
        lr0 += s0; lr1 += s1;

#pragma unroll
        for (int kg = 0; kg < 4; kg++) {
            uint32_t vfh[4][4], vfl[4][4];
#pragma unroll
            for (int cp = 0; cp < 4; cp++) {
                ldm_x4_t(vfh[cp], sVh + (kg * 16 + lrow) * AT_STR + cp * 32 + lcol16);
                ldm_x4_t(vfl[cp], sVl + (kg * 16 + lrow) * AT_STR + cp * 32 + lcol16);
            }
#pragma unroll
            for (int cp = 0; cp < 4; cp++) {
#pragma unroll
                for (int e = 0; e < 2; e++) {
                    const int ng = 2 * cp + e;
                    mma_16816(O[ng], pah[kg], vfh[cp][2 * e], vfh[cp][2 * e + 1]);
                    mma_16816(O[ng], pah[kg], vfl[cp][2 * e], vfl[cp][2 * e + 1]);
                    mma_16816(O[ng], pal[kg], vfh[cp][2 * e], vfh[cp][2 * e + 1]);
                }
            }
        }
    }

    const float inv0 = 1.f / lr0;
    const float inv1 = 1.f / lr1;
    const int r0 = wm + (L >> 2);
    float* o0 = g_attn + (size_t)(b * SEQ + m0 + r0) * 2048 + h * 64 + (L & 3) * 2;
    float* o1 = g_attn + (size_t)(b * SEQ + m0 + r0 + 8) * 2048 + h * 64 + (L & 3) * 2;
#pragma unroll
    for (int ng = 0; ng < 8; ng++) {
        *(float2*)(o0 + ng * 8) = make_float2(O[ng][0] * inv0, O[ng][1] * inv0);
        *(float2*)(o1 + ng * 8) = make_float2(O[ng][2] * inv1, O[ng][3] * inv1);
    }
}

// ---------------------------------------------------------------------------
extern "C" void kernel_launch(void* const* d_in, const int* in_sizes, int n_in,
                              void* d_out, int out_size) {
    const float* x     = (const float*)d_in[0];
    const float* freqs = (const float*)d_in[1];
    const float* wq    = (const float*)d_in[2];
    const float* wk    = (const float*)d_in[3];
    const float* wv    = (const float*)d_in[4];
    const float* wo    = (const float*)d_in[5];
    float* out = (float*)d_out;

    uint32_t *xt, *wqkvt, *wot, *at;
    float *qkv, *attn;
    __nv_bfloat16 *qs, *ks, *vs;
    cudaGetSymbolAddress((void**)&xt, g_xt);
    cudaGetSymbolAddress((void**)&wqkvt, g_wqkvt);
    cudaGetSymbolAddress((void**)&wot, g_wot);
    cudaGetSymbolAddress((void**)&at, g_at);
    cudaGetSymbolAddress((void**)&qkv, g_qkv);
    cudaGetSymbolAddress((void**)&attn, g_attn);
    cudaGetSymbolAddress((void**)&qs, g_qs);
    cudaGetSymbolAddress((void**)&ks, g_ks);
    cudaGetSymbolAddress((void**)&vs, g_vs);

    static bool attr_done = false;
    if (!attr_done) {
        cudaFuncSetAttribute(gemm_f16, cudaFuncAttributeMaxDynamicSharedMemorySize, GSMEM);
        cudaFuncSetAttribute(flash_attn_mma, cudaFuncAttributeMaxDynamicSharedMemorySize, AT_SMEM);
        attr_done = true;
    }

    // 1) pack x, 2) pack merged qkv weights, 3) pack wo
    pack_a<<<4096, 256>>>(x, xt, 0, 256);
    pack_b_qkv<<<(NQKV * 256) / 256, 256>>>(wq, wk, wv, wqkvt, NQKV * 256);
    pack_b<<<(DIMM * 256) / 256, 256>>>(wo, wot, DIMM * 256);

    // 4) fused QKV projection: [4096,3072]
    gemm_f16<<<dim3(NQKV / 128, MROWS / 128), 256, GSMEM>>>(xt, wqkvt, qkv, NQKV);

    // 5) RoPE + hi/lo split for attention inputs
    rope_split<<<MROWS, 256>>>(qkv, freqs);

    // 6) tensor-core attention -> fp32 g_attn
    flash_attn_mma<<<dim3(SEQ / 64, NH, BB), 128, AT_SMEM>>>(qs, ks, vs);

    // 7) pack attn output for O projection
    pack_a<<<4096, 256>>>(attn, at, 0, 256);

    // 8) O projection
    gemm_f16<<<dim3(DIMM / 128, MROWS / 128), 256, GSMEM>>>(at, wot, out, DIMM);
}

// round 9
// speedup vs baseline: 3.3571x; 1.4616x over previous
#include <cuda_runtime.h>
#include <cuda_bf16.h>
#include <cuda_fp16.h>
#include <cstdint>
#include <cstddef>

// Problem constants
constexpr int BB   = 2;
constexpr int SEQ  = 2048;
constexpr int DIMM = 2048;
constexpr int NH   = 32;
constexpr int NKV  = 8;
constexpr int HDIM = 64;
constexpr int MROWS = BB * SEQ;                    // 4096
constexpr int NQKV  = NH * HDIM + 2 * NKV * HDIM;  // 3072

// ---------------------------------------------------------------------------
// Scratch (device globals; allocation-free rule)
// ---------------------------------------------------------------------------
__device__ uint32_t g_xt[MROWS * DIMM / 2];         // packed x           16 MB
__device__ uint32_t g_wqkvt[NQKV * DIMM / 2];       // packed wq|wk|wv    12 MB
__device__ uint32_t g_wot[DIMM * DIMM / 2];         // packed wo           8 MB
__device__ uint32_t g_at[MROWS * DIMM / 2];         // packed attn out    16 MB
__device__ float g_qkv[MROWS * NQKV];               // q|k|v fp32         48 MB
__device__ float g_attn[MROWS * NH * HDIM];         // attn out fp32      32 MB
// attention inputs, fp16, 64 per row
__device__ __half g_qs[BB * NH * SEQ * HDIM];       // 16 MB (q prescaled by 1/8)
__device__ __half g_ks[BB * NKV * SEQ * HDIM];      // 4 MB
__device__ __half g_vs[BB * NKV * SEQ * HDIM];      // 4 MB

// ---------------------------------------------------------------------------
// Helpers
// ---------------------------------------------------------------------------
__device__ __forceinline__ uint32_t smem_u32(const void* p) {
    uint32_t a;
    asm("{ .reg .u64 t; cvta.to.shared.u64 t, %1; cvt.u32.u64 %0, t; }" : "=r"(a) : "l"(p));
    return a;
}
__device__ __forceinline__ void cp_async16(uint32_t dst, const void* src) {
    asm volatile("cp.async.cg.shared.global [%0], [%1], 16;" :: "r"(dst), "l"(src));
}
__device__ __forceinline__ void cp_commit() { asm volatile("cp.async.commit_group;" ::: "memory"); }

__device__ __forceinline__ void lds128(uint32_t* r, uint32_t addr) {
    asm volatile("ld.shared.v4.b32 {%0,%1,%2,%3}, [%4];"
        : "=r"(r[0]), "=r"(r[1]), "=r"(r[2]), "=r"(r[3]) : "r"(addr));
}
__device__ __forceinline__ void ldm_x4(uint32_t* r, uint32_t addr) {
    asm volatile("ldmatrix.sync.aligned.m8n8.x4.shared.b16 {%0,%1,%2,%3}, [%4];"
        : "=r"(r[0]), "=r"(r[1]), "=r"(r[2]), "=r"(r[3]) : "r"(addr));
}
__device__ __forceinline__ void ldm_x4_t(uint32_t* r, uint32_t addr) {
    asm volatile("ldmatrix.sync.aligned.m8n8.x4.trans.shared.b16 {%0,%1,%2,%3}, [%4];"
        : "=r"(r[0]), "=r"(r[1]), "=r"(r[2]), "=r"(r[3]) : "r"(addr));
}
__device__ __forceinline__ void mma_f16(float* d, const uint32_t* a, uint32_t b0, uint32_t b1) {
    asm volatile("mma.sync.aligned.m16n8k16.row.col.f32.f16.f16.f32 "
        "{%0,%1,%2,%3}, {%4,%5,%6,%7}, {%8,%9}, {%0,%1,%2,%3};"
        : "+f"(d[0]), "+f"(d[1]), "+f"(d[2]), "+f"(d[3])
        : "r"(a[0]), "r"(a[1]), "r"(a[2]), "r"(a[3]), "r"(b0), "r"(b1));
}
__device__ __forceinline__ uint32_t f2h2(float lo, float hi) {
    __half2 h = __floats2half2_rn(lo, hi);
    return *(uint32_t*)&h;
}
__device__ __forceinline__ float ex2f(float x) {
    float r;
    asm("ex2.approx.f32 %0, %1;" : "=f"(r) : "f"(x));
    return r;
}

// ---------------------------------------------------------------------------
// pack_a: fp32 [rows][2048] -> fp16 A-fragment pack (m16n8k16).
// ---------------------------------------------------------------------------
__global__ __launch_bounds__(256) void pack_a(const float* __restrict__ src,
                                              uint32_t* __restrict__ dst,
                                              int mb0, int nmb) {
    int idx = blockIdx.x * 256 + threadIdx.x;
    if (idx >= nmb * 4096) return;
    int lane = idx & 31;
    int kc16 = (idx >> 5) & 127;
    int mb = (idx >> 12) + mb0;
    int r = lane >> 2;
    int c2 = kc16 * 16 + (lane & 3) * 2;
    const float* s = src + (size_t)mb * 16 * 2048;
    uint4 o;
    o.x = f2h2(s[(size_t)r * 2048 + c2],        s[(size_t)r * 2048 + c2 + 1]);
    o.y = f2h2(s[(size_t)(r + 8) * 2048 + c2],  s[(size_t)(r + 8) * 2048 + c2 + 1]);
    o.z = f2h2(s[(size_t)r * 2048 + c2 + 8],    s[(size_t)r * 2048 + c2 + 9]);
    o.w = f2h2(s[(size_t)(r + 8) * 2048 + c2 + 8], s[(size_t)(r + 8) * 2048 + c2 + 9]);
    ((uint4*)dst)[(size_t)mb * 4096 + (idx & 4095)] = o;
}

// ---------------------------------------------------------------------------
// pack_b: weights [N][2048] -> fp16 B-fragment pack.
// ---------------------------------------------------------------------------
__global__ __launch_bounds__(256) void pack_b(const float* __restrict__ src,
                                              uint32_t* __restrict__ dst, int total) {
    int idx = blockIdx.x * 256 + threadIdx.x;
    if (idx >= total) return;
    int lane = idx & 31;
    int kc32 = (idx >> 5) & 63;
    int nb = idx >> 11;
    int n = nb * 8 + (lane >> 2);
    int k2 = kc32 * 32 + (lane & 3) * 2;
    const float* s = src + (size_t)n * 2048 + k2;
    uint4 o;
    o.x = f2h2(s[0],  s[1]);
    o.y = f2h2(s[8],  s[9]);
    o.z = f2h2(s[16], s[17]);
    o.w = f2h2(s[24], s[25]);
    ((uint4*)dst)[idx] = o;
}

__global__ __launch_bounds__(256) void pack_b_qkv(const float* __restrict__ wq,
                                                  const float* __restrict__ wk,
                                                  const float* __restrict__ wv,
                                                  uint32_t* __restrict__ dst, int total) {
    int idx = blockIdx.x * 256 + threadIdx.x;
    if (idx >= total) return;
    int lane = idx & 31;
    int kc32 = (idx >> 5) & 63;
    int nb = idx >> 11;
    int n = nb * 8 + (lane >> 2);
    int k2 = kc32 * 32 + (lane & 3) * 2;
    const float* s;
    if (n < 2048)      s = wq + (size_t)n * 2048 + k2;
    else if (n < 2560) s = wk + (size_t)(n - 2048) * 2048 + k2;
    else               s = wv + (size_t)(n - 2560) * 2048 + k2;
    uint4 o;
    o.x = f2h2(s[0],  s[1]);
    o.y = f2h2(s[8],  s[9]);
    o.z = f2h2(s[16], s[17]);
    o.w = f2h2(s[24], s[25]);
    ((uint4*)dst)[idx] = o;
}

// ---------------------------------------------------------------------------
// fp16 GEMM (unchanged from R8): CTA 128x128, warp 64x32, K-chunk 32,
// 4-stage cp.async pipeline, 2 CTAs/SM.
// ---------------------------------------------------------------------------
constexpr int FSTAGE = 16384;
constexpr int GSMEM  = 4 * FSTAGE;

__global__ __launch_bounds__(256, 2)
void gemm_f16(const uint32_t* __restrict__ A, const uint32_t* __restrict__ B,
              float* __restrict__ C, int Ntot) {
    extern __shared__ __align__(128) char dsm[];
    const int tid = threadIdx.x;
    const int wid = tid >> 5;
    const int L = tid & 31;
    const uint32_t base = smem_u32(dsm);
    const int bm = blockIdx.y * 128;
    const int bn = blockIdx.x * 128;
    const uint32_t* Ab = A + (size_t)(bm >> 4) * 16384;
    const uint32_t* Bb = B + (size_t)(bn >> 3) * 8192;

    float acc[4][4][4];
#pragma unroll
    for (int i = 0; i < 4; i++)
#pragma unroll
        for (int j = 0; j < 4; j++)
#pragma unroll
            for (int q = 0; q < 4; q++) acc[i][j][q] = 0.f;

    auto load_stage = [&](int s, int c) {
        const uint32_t sb = base + s * FSTAGE;
#pragma unroll
        for (int u = 0; u < 2; u++) {
            int e = tid + u * 256;
            int lane = e & 31, kcl = (e >> 5) & 1, mb = e >> 6;
            cp_async16(sb + e * 16,
                       Ab + (((size_t)mb * 128 + c * 2 + kcl) * 32 + lane) * 4);
        }
#pragma unroll
        for (int u = 0; u < 2; u++) {
            int e = tid + u * 256;
            int lane = e & 31, nb = e >> 5;
            cp_async16(sb + 8192 + e * 16,
                       Bb + (((size_t)nb * 64 + c) * 32 + lane) * 4);
        }
    };

    load_stage(0, 0); cp_commit();
    load_stage(1, 1); cp_commit();
    load_stage(2, 2); cp_commit();

    const int wmb = (wid >> 2) * 4;
    const int wnb = (wid & 3) * 4;

    for (int i = 0; i < 64; i++) {
        if (i + 3 < 64) load_stage((i + 3) & 3, i + 3);
        cp_commit();
        asm volatile("cp.async.wait_group 3;" ::: "memory");
        __syncthreads();

        const uint32_t sA = base + (i & 3) * FSTAGE;
        const uint32_t sB = sA + 8192;
        uint32_t b[4][4];
#pragma unroll
        for (int g = 0; g < 4; g++)
            lds128(b[g], sB + (((wnb + g) * 32) + L) * 16);
#pragma unroll
        for (int kcl = 0; kcl < 2; kcl++) {
            uint32_t a[4][4];
#pragma unroll
            for (int am = 0; am < 4; am++)
                lds128(a[am], sA + (((wmb + am) * 2 + kcl) * 32 + L) * 16);
#pragma unroll
            for (int am = 0; am < 4; am++)
#pragma unroll
                for (int g = 0; g < 4; g++)
                    mma_f16(acc[am][g], a[am], b[g][2 * kcl], b[g][2 * kcl + 1]);
        }
        __syncthreads();
    }

#pragma unroll
    for (int am = 0; am < 4; am++) {
        int row = bm + (wid >> 2) * 64 + am * 16 + (L >> 2);
#pragma unroll
        for (int g = 0; g < 4; g++) {
            int col = bn + (wid & 3) * 32 + g * 8 + (L & 3) * 2;
            *(float2*)(C + (size_t)row * Ntot + col) = make_float2(acc[am][g][0], acc[am][g][1]);
            *(float2*)(C + (size_t)(row + 8) * Ntot + col) = make_float2(acc[am][g][2], acc[am][g][3]);
        }
    }
}

// ---------------------------------------------------------------------------
// Fused RoPE + fp16 convert for attention inputs.
// ---------------------------------------------------------------------------
__global__ __launch_bounds__(256) void rope_half(const float* __restrict__ qkv,
                                                 const float* __restrict__ freqs) {
    const int ml = blockIdx.x;            // b*SEQ + l
    const int l = ml & (SEQ - 1);
    const int b = ml >> 11;
    const float* row = qkv + (size_t)ml * NQKV;

#pragma unroll
    for (int it = 0; it < 6; it++) {
        int u = threadIdx.x + it * 256;
        float v0, v1;
        __half* dst;
        if (u < 1024) {                   // q
            int h = u >> 5, p = u & 31;
            float2 t = *(const float2*)(row + h * 64 + 2 * p);
            float c = freqs[l * 32 + p];
            float s = freqs[SEQ * 32 + l * 32 + p];
            v0 = (t.x * c - t.y * s) * 0.125f;
            v1 = (t.x * s + t.y * c) * 0.125f;
            dst = g_qs + ((size_t)(b * NH + h) * SEQ + l) * 64 + 2 * p;
        } else if (u < 1280) {            // k
            int u2 = u - 1024;
            int kh = u2 >> 5, p = u2 & 31;
            float2 t = *(const float2*)(row + 2048 + kh * 64 + 2 * p);
            float c = freqs[l * 32 + p];
            float s = freqs[SEQ * 32 + l * 32 + p];
            v0 = t.x * c - t.y * s;
            v1 = t.x * s + t.y * c;
            dst = g_ks + ((size_t)(b * NKV + kh) * SEQ + l) * 64 + 2 * p;
        } else {                          // v
            int u2 = u - 1280;
            int kh = u2 >> 5, p = u2 & 31;
            float2 t = *(const float2*)(row + 2560 + kh * 64 + 2 * p);
            v0 = t.x; v1 = t.y;
            dst = g_vs + ((size_t)(b * NKV + kh) * SEQ + l) * 64 + 2 * p;
        }
        *(uint32_t*)dst = f2h2(v0, v1);
    }
}

// ---------------------------------------------------------------------------
// Single-pass fp16 causal flash attention.
// grid (SEQ/128, NH, BB); 256 threads = 8 warps x 16 query rows.
// smem: Q 128x144B | K/V double-buffered 64x144B each.
// ---------------------------------------------------------------------------
constexpr int FA_STR = 144;
constexpr int FA_Q   = 0;                          // 18432 B
constexpr int FA_KV  = 128 * FA_STR;               // K0 V0 K1 V1, 9216 each
constexpr int FA_SMEM = FA_KV + 4 * 64 * FA_STR;   // 55296
constexpr float LOG2E = 1.4426950408889634f;

__global__ __launch_bounds__(256, 2)
void flash_attn_f16(const __half* __restrict__ Qs,
                    const __half* __restrict__ Ks,
                    const __half* __restrict__ Vs) {
    extern __shared__ __align__(128) char fsm[];
    const uint32_t base = smem_u32(fsm);
    const uint32_t sQ = base + FA_Q;

    const int tid = threadIdx.x;
    const int wid = tid >> 5;
    const int L = tid & 31;
    const int wm = wid * 16;
    const uint32_t lrow = L & 15;
    const uint32_t lcol16 = (L >> 4) * 16;

    const int m0 = blockIdx.x * 128;
    const int h = blockIdx.y;
    const int b = blockIdx.z;
    const int kvh = h >> 2;

    // ---- load Q tile ----
    const __half* qsrc = Qs + ((size_t)(b * NH + h) * SEQ + m0) * 64;
#pragma unroll
    for (int u = 0; u < 4; u++) {
        int e = tid + u * 256;
        int row = e >> 3, ch = e & 7;
        cp_async16(sQ + row * FA_STR + ch * 16, qsrc + (size_t)row * 64 + ch * 8);
    }
    cp_commit();
    asm volatile("cp.async.wait_group 0;" ::: "memory");
    __syncthreads();

    uint32_t qf[4][4];
#pragma unroll
    for (int kg = 0; kg < 4; kg++)
        ldm_x4(qf[kg], sQ + (wm + lrow) * FA_STR + kg * 32 + lcol16);

    float O[8][4];
#pragma unroll
    for (int i = 0; i < 8; i++)
#pragma unroll
        for (int j = 0; j < 4; j++) O[i][j] = 0.f;
    float mr0 = -1e30f, mr1 = -1e30f, lr0 = 0.f, lr1 = 0.f;

    const __half* ksrc = Ks + (size_t)(b * NKV + kvh) * SEQ * 64;
    const __half* vsrc = Vs + (size_t)(b * NKV + kvh) * SEQ * 64;

    auto load_kv = [&](int t) {
        const int n0 = t * 64;
        const uint32_t kb = base + FA_KV + (t & 1) * 18432;
        const uint32_t vb = kb + 9216;
#pragma unroll
        for (int u = 0; u < 2; u++) {
            int e = tid + u * 256;
            int row = e >> 3, ch = e & 7;
            cp_async16(kb + row * FA_STR + ch * 16, ksrc + (size_t)(n0 + row) * 64 + ch * 8);
            cp_async16(vb + row * FA_STR + ch * 16, vsrc + (size_t)(n0 + row) * 64 + ch * 8);
        }
    };

    const int nT = m0 / 64 + 2;
    load_kv(0); cp_commit();

    for (int t = 0; t < nT; t++) {
        if (t + 1 < nT) load_kv(t + 1);
        cp_commit();
        asm volatile("cp.async.wait_group 1;" ::: "memory");
        __syncthreads();

        const int n0 = t * 64;
        const uint32_t kb = base + FA_KV + (t & 1) * 18432;
        const uint32_t vb = kb + 9216;
        const bool active = (n0 <= m0 + wm + 15);

        if (active) {
            // ---- S = Q K^T ----
            float S[8][4];
#pragma unroll
            for (int i = 0; i < 8; i++)
#pragma unroll
                for (int j = 0; j < 4; j++) S[i][j] = 0.f;

#pragma unroll
            for (int kg = 0; kg < 4; kg++) {
                uint32_t kf[4][4];
#pragma unroll
                for (int nn = 0; nn < 4; nn++)
                    ldm_x4(kf[nn], kb + (nn * 16 + lrow) * FA_STR + kg * 32 + lcol16);
#pragma unroll
                for (int ng = 0; ng < 8; ng++)
                    mma_f16(S[ng], qf[kg], kf[ng >> 1][ng & 1], kf[ng >> 1][2 + (ng & 1)]);
            }

            // ---- causal mask (tiles overlapping the diagonal) ----
            const int r0 = m0 + wm + (L >> 2);
            const int r1 = r0 + 8;
            if (n0 + 63 > m0 + wm) {
#pragma unroll
                for (int ng = 0; ng < 8; ng++) {
                    int c0 = n0 + ng * 8 + (L & 3) * 2;
                    if (c0 > r0)     S[ng][0] = -1e30f;
                    if (c0 + 1 > r0) S[ng][1] = -1e30f;
                    if (c0 > r1)     S[ng][2] = -1e30f;
                    if (c0 + 1 > r1) S[ng][3] = -1e30f;
                }
            }

            // ---- online softmax ----
            float t0 = -1e30f, t1 = -1e30f;
#pragma unroll
            for (int ng = 0; ng < 8; ng++) {
                t0 = fmaxf(t0, fmaxf(S[ng][0], S[ng][1]));
                t1 = fmaxf(t1, fmaxf(S[ng][2], S[ng][3]));
            }
            t0 = fmaxf(t0, __shfl_xor_sync(0xffffffffu, t0, 1));
            t0 = fmaxf(t0, __shfl_xor_sync(0xffffffffu, t0, 2));
            t1 = fmaxf(t1, __shfl_xor_sync(0xffffffffu, t1, 1));
            t1 = fmaxf(t1, __shfl_xor_sync(0xffffffffu, t1, 2));

            float mn0 = fmaxf(mr0, t0), mn1 = fmaxf(mr1, t1);
            float corr0 = ex2f((mr0 - mn0) * LOG2E);
            float corr1 = ex2f((mr1 - mn1) * LOG2E);
            lr0 *= corr0; lr1 *= corr1;
#pragma unroll
            for (int ng = 0; ng < 8; ng++) {
                O[ng][0] *= corr0; O[ng][1] *= corr0;
                O[ng][2] *= corr1; O[ng][3] *= corr1;
            }
            mr0 = mn0; mr1 = mn1;
            const float mb0 = mn0 * LOG2E, mb1 = mn1 * LOG2E;

            uint32_t pa[4][4];
            float s0 = 0.f, s1 = 0.f;
#pragma unroll
            for (int kg = 0; kg < 4; kg++) {
                float p[8];
#pragma unroll
                for (int e = 0; e < 2; e++) {
                    const int g = 2 * kg + e;
                    p[4 * e + 0] = ex2f(fmaf(S[g][0], LOG2E, -mb0));
                    p[4 * e + 1] = ex2f(fmaf(S[g][1], LOG2E, -mb0));
                    p[4 * e + 2] = ex2f(fmaf(S[g][2], LOG2E, -mb1));
                    p[4 * e + 3] = ex2f(fmaf(S[g][3], LOG2E, -mb1));
                    s0 += p[4 * e] + p[4 * e + 1];
                    s1 += p[4 * e + 2] + p[4 * e + 3];
                }
                pa[kg][0] = f2h2(p[0], p[1]);
                pa[kg][1] = f2h2(p[2], p[3]);
                pa[kg][2] = f2h2(p[4], p[5]);
                pa[kg][3] = f2h2(p[6], p[7]);
            }
            s0 += __shfl_xor_sync(0xffffffffu, s0, 1);
            s0 += __shfl_xor_sync(0xffffffffu, s0, 2);
            s1 += __shfl_xor_sync(0xffffffffu, s1, 1);
            s1 += __shfl_xor_sync(0xffffffffu, s1, 2);
            lr0 += s0; lr1 += s1;

            // ---- O += P V ----
#pragma unroll
            for (int kg = 0; kg < 4; kg++) {
                uint32_t vf[4][4];
#pragma unroll
                for (int cp = 0; cp < 4; cp++)
                    ldm_x4_t(vf[cp], vb + (kg * 16 + lrow) * FA_STR + cp * 32 + lcol16);
#pragma unroll
                for (int cp = 0; cp < 4; cp++) {
#pragma unroll
                    for (int e = 0; e < 2; e++) {
                        const int ng = 2 * cp + e;
                        mma_f16(O[ng], pa[kg], vf[cp][2 * e], vf[cp][2 * e + 1]);
                    }
                }
            }
        }
        __syncthreads();
    }

    // ---- write out ----
    const float inv0 = 1.f / lr0;
    const float inv1 = 1.f / lr1;
    const int r0 = m0 + wm + (L >> 2);
    float* o0 = g_attn + (size_t)(b * SEQ + r0) * 2048 + h * 64 + (L & 3) * 2;
    float* o1 = o0 + (size_t)8 * 2048;
#pragma unroll
    for (int ng = 0; ng < 8; ng++) {
        *(float2*)(o0 + ng * 8) = make_float2(O[ng][0] * inv0, O[ng][1] * inv0);
        *(float2*)(o1 + ng * 8) = make_float2(O[ng][2] * inv1, O[ng][3] * inv1);
    }
}

// ---------------------------------------------------------------------------
extern "C" void kernel_launch(void* const* d_in, const int* in_sizes, int n_in,
                              void* d_out, int out_size) {
    const float* x     = (const float*)d_in[0];
    const float* freqs = (const float*)d_in[1];
    const float* wq    = (const float*)d_in[2];
    const float* wk    = (const float*)d_in[3];
    const float* wv    = (const float*)d_in[4];
    const float* wo    = (const float*)d_in[5];
    float* out = (float*)d_out;

    uint32_t *xt, *wqkvt, *wot, *at;
    float *qkv, *attn;
    __half *qs, *ks, *vs;
    cudaGetSymbolAddress((void**)&xt, g_xt);
    cudaGetSymbolAddress((void**)&wqkvt, g_wqkvt);
    cudaGetSymbolAddress((void**)&wot, g_wot);
    cudaGetSymbolAddress((void**)&at, g_at);
    cudaGetSymbolAddress((void**)&qkv, g_qkv);
    cudaGetSymbolAddress((void**)&attn, g_attn);
    cudaGetSymbolAddress((void**)&qs, g_qs);
    cudaGetSymbolAddress((void**)&ks, g_ks);
    cudaGetSymbolAddress((void**)&vs, g_vs);

    static bool attr_done = false;
    if (!attr_done) {
        cudaFuncSetAttribute(gemm_f16, cudaFuncAttributeMaxDynamicSharedMemorySize, GSMEM);
        cudaFuncSetAttribute(flash_attn_f16, cudaFuncAttributeMaxDynamicSharedMemorySize, FA_SMEM);
        attr_done = true;
    }

    // 1) pack x, 2) pack merged qkv weights, 3) pack wo
    pack_a<<<4096, 256>>>(x, xt, 0, 256);
    pack_b_qkv<<<(NQKV * 256) / 256, 256>>>(wq, wk, wv, wqkvt, NQKV * 256);
    pack_b<<<(DIMM * 256) / 256, 256>>>(wo, wot, DIMM * 256);

    // 4) fused QKV projection
    gemm_f16<<<dim3(NQKV / 128, MROWS / 128), 256, GSMEM>>>(xt, wqkvt, qkv, NQKV);

    // 5) RoPE + fp16 convert
    rope_half<<<MROWS, 256>>>(qkv, freqs);

    // 6) single-pass fp16 attention -> fp32 g_attn
    flash_attn_f16<<<dim3(SEQ / 128, NH, BB), 256, FA_SMEM>>>(qs, ks, vs);

    // 7) pack attn output, 8) O projection
    pack_a<<<4096, 256>>>(attn, at, 0, 256);
    gemm_f16<<<dim3(DIMM / 128, MROWS / 128), 256, GSMEM>>>(at, wot, out, DIMM);
}

// round 10
// speedup vs baseline: 3.4910x; 1.0399x over previous
#include <cuda_runtime.h>
#include <cuda_fp16.h>
#include <cstdint>
#include <cstddef>

// Problem constants
constexpr int BB   = 2;
constexpr int SEQ  = 2048;
constexpr int DIMM = 2048;
constexpr int NH   = 32;
constexpr int NKV  = 8;
constexpr int HDIM = 64;
constexpr int MROWS = BB * SEQ;                    // 4096
constexpr int NQKV  = NH * HDIM + 2 * NKV * HDIM;  // 3072

// ---------------------------------------------------------------------------
// Scratch (device globals; allocation-free rule)
// Fragment-packed fp16 operands (m16n8k16):
//  A-pack: [mb=row/16][kc16=k/16 (128)][lane][4 half2 words]
//  B-pack: [nb=n/8][kc32=k/32 (64)][lane][4 half2 words]
// ---------------------------------------------------------------------------
__device__ uint32_t g_xt[MROWS * DIMM / 2];         // packed x           16 MB
__device__ uint32_t g_wqkvt[NQKV * DIMM / 2];       // packed wq|wk|wv    12 MB
__device__ uint32_t g_wot[DIMM * DIMM / 2];         // packed wo           8 MB
__device__ uint32_t g_at[MROWS * DIMM / 2];         // packed attn out    16 MB
// attention inputs, fp16, 64 per row
__device__ __half g_qs[BB * NH * SEQ * HDIM];       // 16 MB (q roped, /8)
__device__ __half g_ks[BB * NKV * SEQ * HDIM];      // 4 MB  (k roped)
__device__ __half g_vs[BB * NKV * SEQ * HDIM];      // 4 MB

// ---------------------------------------------------------------------------
// Helpers
// ---------------------------------------------------------------------------
__device__ __forceinline__ uint32_t smem_u32(const void* p) {
    uint32_t a;
    asm("{ .reg .u64 t; cvta.to.shared.u64 t, %1; cvt.u32.u64 %0, t; }" : "=r"(a) : "l"(p));
    return a;
}
__device__ __forceinline__ void cp_async16(uint32_t dst, const void* src) {
    asm volatile("cp.async.cg.shared.global [%0], [%1], 16;" :: "r"(dst), "l"(src));
}
__device__ __forceinline__ void cp_commit() { asm volatile("cp.async.commit_group;" ::: "memory"); }

__device__ __forceinline__ void lds128(uint32_t* r, uint32_t addr) {
    asm volatile("ld.shared.v4.b32 {%0,%1,%2,%3}, [%4];"
        : "=r"(r[0]), "=r"(r[1]), "=r"(r[2]), "=r"(r[3]) : "r"(addr));
}
__device__ __forceinline__ void ldm_x4(uint32_t* r, uint32_t addr) {
    asm volatile("ldmatrix.sync.aligned.m8n8.x4.shared.b16 {%0,%1,%2,%3}, [%4];"
        : "=r"(r[0]), "=r"(r[1]), "=r"(r[2]), "=r"(r[3]) : "r"(addr));
}
__device__ __forceinline__ void ldm_x4_t(uint32_t* r, uint32_t addr) {
    asm volatile("ldmatrix.sync.aligned.m8n8.x4.trans.shared.b16 {%0,%1,%2,%3}, [%4];"
        : "=r"(r[0]), "=r"(r[1]), "=r"(r[2]), "=r"(r[3]) : "r"(addr));
}
__device__ __forceinline__ void mma_f16(float* d, const uint32_t* a, uint32_t b0, uint32_t b1) {
    asm volatile("mma.sync.aligned.m16n8k16.row.col.f32.f16.f16.f32 "
        "{%0,%1,%2,%3}, {%4,%5,%6,%7}, {%8,%9}, {%0,%1,%2,%3};"
        : "+f"(d[0]), "+f"(d[1]), "+f"(d[2]), "+f"(d[3])
        : "r"(a[0]), "r"(a[1]), "r"(a[2]), "r"(a[3]), "r"(b0), "r"(b1));
}
__device__ __forceinline__ uint32_t f2h2(float lo, float hi) {
    __half2 h = __floats2half2_rn(lo, hi);
    return *(uint32_t*)&h;
}
__device__ __forceinline__ float ex2f(float x) {
    float r;
    asm("ex2.approx.f32 %0, %1;" : "=f"(r) : "f"(x));
    return r;
}

// ---------------------------------------------------------------------------
// pack_a: fp32 [rows][2048] -> fp16 A-fragment pack (m16n8k16).
// ---------------------------------------------------------------------------
__global__ __launch_bounds__(256) void pack_a(const float* __restrict__ src,
                                              uint32_t* __restrict__ dst,
                                              int mb0, int nmb) {
    int idx = blockIdx.x * 256 + threadIdx.x;
    if (idx >= nmb * 4096) return;
    int lane = idx & 31;
    int kc16 = (idx >> 5) & 127;
    int mb = (idx >> 12) + mb0;
    int r = lane >> 2;
    int c2 = kc16 * 16 + (lane & 3) * 2;
    const float* s = src + (size_t)mb * 16 * 2048;
    uint4 o;
    o.x = f2h2(s[(size_t)r * 2048 + c2],        s[(size_t)r * 2048 + c2 + 1]);
    o.y = f2h2(s[(size_t)(r + 8) * 2048 + c2],  s[(size_t)(r + 8) * 2048 + c2 + 1]);
    o.z = f2h2(s[(size_t)r * 2048 + c2 + 8],    s[(size_t)r * 2048 + c2 + 9]);
    o.w = f2h2(s[(size_t)(r + 8) * 2048 + c2 + 8], s[(size_t)(r + 8) * 2048 + c2 + 9]);
    ((uint4*)dst)[(size_t)mb * 4096 + (idx & 4095)] = o;
}

// ---------------------------------------------------------------------------
// pack_b: weights [N][2048] -> fp16 B-fragment pack.
// ---------------------------------------------------------------------------
__global__ __launch_bounds__(256) void pack_b(const float* __restrict__ src,
                                              uint32_t* __restrict__ dst, int total) {
    int idx = blockIdx.x * 256 + threadIdx.x;
    if (idx >= total) return;
    int lane = idx & 31;
    int kc32 = (idx >> 5) & 63;
    int nb = idx >> 11;
    int n = nb * 8 + (lane >> 2);
    int k2 = kc32 * 32 + (lane & 3) * 2;
    const float* s = src + (size_t)n * 2048 + k2;
    uint4 o;
    o.x = f2h2(s[0],  s[1]);
    o.y = f2h2(s[8],  s[9]);
    o.z = f2h2(s[16], s[17]);
    o.w = f2h2(s[24], s[25]);
    ((uint4*)dst)[idx] = o;
}

__global__ __launch_bounds__(256) void pack_b_qkv(const float* __restrict__ wq,
                                                  const float* __restrict__ wk,
                                                  const float* __restrict__ wv,
                                                  uint32_t* __restrict__ dst, int total) {
    int idx = blockIdx.x * 256 + threadIdx.x;
    if (idx >= total) return;
    int lane = idx & 31;
    int kc32 = (idx >> 5) & 63;
    int nb = idx >> 11;
    int n = nb * 8 + (lane >> 2);
    int k2 = kc32 * 32 + (lane & 3) * 2;
    const float* s;
    if (n < 2048)      s = wq + (size_t)n * 2048 + k2;
    else if (n < 2560) s = wk + (size_t)(n - 2048) * 2048 + k2;
    else               s = wv + (size_t)(n - 2560) * 2048 + k2;
    uint4 o;
    o.x = f2h2(s[0],  s[1]);
    o.y = f2h2(s[8],  s[9]);
    o.z = f2h2(s[16], s[17]);
    o.w = f2h2(s[24], s[25]);
    ((uint4*)dst)[idx] = o;
}

// ---------------------------------------------------------------------------
// GEMM mainloop (shared by both GEMMs): CTA 128x128, warp 64x32, K-chunk 32,
// 4-stage cp.async pipeline, ONE sync per iteration.
// ---------------------------------------------------------------------------
constexpr int FSTAGE = 16384;
constexpr int GSMEM  = 4 * FSTAGE;

struct GemmCtx {
    float acc[4][4][4];
    int bm, bn, wid, L;
};

__device__ __forceinline__ void gemm_mainloop(const uint32_t* __restrict__ A,
                                              const uint32_t* __restrict__ B,
                                              GemmCtx& cx, char* dsm) {
    const int tid = threadIdx.x;
    const int wid = tid >> 5;
    const int L = tid & 31;
    const uint32_t base = smem_u32(dsm);
    cx.bm = blockIdx.y * 128;
    cx.bn = blockIdx.x * 128;
    cx.wid = wid; cx.L = L;
    const uint32_t* Ab = A + (size_t)(cx.bm >> 4) * 16384;
    const uint32_t* Bb = B + (size_t)(cx.bn >> 3) * 8192;

#pragma unroll
    for (int i = 0; i < 4; i++)
#pragma unroll
        for (int j = 0; j < 4; j++)
#pragma unroll
            for (int q = 0; q < 4; q++) cx.acc[i][j][q] = 0.f;

    auto load_stage = [&](int s, int c) {
        const uint32_t sb = base + s * FSTAGE;
#pragma unroll
        for (int u = 0; u < 2; u++) {
            int e = tid + u * 256;
            int lane = e & 31, kcl = (e >> 5) & 1, mb = e >> 6;
            cp_async16(sb + e * 16,
                       Ab + (((size_t)mb * 128 + c * 2 + kcl) * 32 + lane) * 4);
        }
#pragma unroll
        for (int u = 0; u < 2; u++) {
            int e = tid + u * 256;
            int lane = e & 31, nb = e >> 5;
            cp_async16(sb + 8192 + e * 16,
                       Bb + (((size_t)nb * 64 + c) * 32 + lane) * 4);
        }
    };

    load_stage(0, 0); cp_commit();
    load_stage(1, 1); cp_commit();
    load_stage(2, 2); cp_commit();

    const int wmb = (wid >> 2) * 4;
    const int wnb = (wid & 3) * 4;

    for (int i = 0; i < 64; i++) {
        asm volatile("cp.async.wait_group 2;" ::: "memory");
        __syncthreads();
        if (i + 3 < 64) load_stage((i + 3) & 3, i + 3);
        cp_commit();

        const uint32_t sA = base + (i & 3) * FSTAGE;
        const uint32_t sB = sA + 8192;
        uint32_t b[4][4];
#pragma unroll
        for (int g = 0; g < 4; g++)
            lds128(b[g], sB + (((wnb + g) * 32) + L) * 16);
#pragma unroll
        for (int kcl = 0; kcl < 2; kcl++) {
            uint32_t a[4][4];
#pragma unroll
            for (int am = 0; am < 4; am++)
                lds128(a[am], sA + (((wmb + am) * 2 + kcl) * 32 + L) * 16);
#pragma unroll
            for (int am = 0; am < 4; am++)
#pragma unroll
                for (int g = 0; g < 4; g++)
                    mma_f16(cx.acc[am][g], a[am], b[g][2 * kcl], b[g][2 * kcl + 1]);
        }
    }
}

// ---------------------------------------------------------------------------
// O-projection GEMM: plain fp32 epilogue to d_out.
// ---------------------------------------------------------------------------
__global__ __launch_bounds__(256, 2)
void gemm_f16(const uint32_t* __restrict__ A, const uint32_t* __restrict__ B,
              float* __restrict__ C, int Ntot) {
    extern __shared__ __align__(128) char dsm[];
    GemmCtx cx;
    gemm_mainloop(A, B, cx, dsm);
#pragma unroll
    for (int am = 0; am < 4; am++) {
        int row = cx.bm + (cx.wid >> 2) * 64 + am * 16 + (cx.L >> 2);
#pragma unroll
        for (int g = 0; g < 4; g++) {
            int col = cx.bn + (cx.wid & 3) * 32 + g * 8 + (cx.L & 3) * 2;
            *(float2*)(C + (size_t)row * Ntot + col) = make_float2(cx.acc[am][g][0], cx.acc[am][g][1]);
            *(float2*)(C + (size_t)(row + 8) * Ntot + col) = make_float2(cx.acc[am][g][2], cx.acc[am][g][3]);
        }
    }
}

// ---------------------------------------------------------------------------
// QKV GEMM with fused RoPE + fp16 epilogue writing g_qs/g_ks/g_vs.
// Accumulator pair (c0,c1) = RoPE (real, imag) pair directly.
// ---------------------------------------------------------------------------
__global__ __launch_bounds__(256, 2)
void gemm_qkv(const uint32_t* __restrict__ A, const uint32_t* __restrict__ B,
              const float* __restrict__ freqs) {
    extern __shared__ __align__(128) char dsm[];
    GemmCtx cx;
    gemm_mainloop(A, B, cx, dsm);

#pragma unroll
    for (int am = 0; am < 4; am++) {
        int row0 = cx.bm + (cx.wid >> 2) * 64 + am * 16 + (cx.L >> 2);
#pragma unroll
        for (int half = 0; half < 2; half++) {
            const int row = row0 + half * 8;
            const int l = row & (SEQ - 1);
            const int b = row >> 11;
#pragma unroll
            for (int g = 0; g < 4; g++) {
                int col = cx.bn + (cx.wid & 3) * 32 + g * 8 + (cx.L & 3) * 2;
                float v0 = cx.acc[am][g][2 * half];
                float v1 = cx.acc[am][g][2 * half + 1];
                if (col < 2048) {                         // q: rope + 0.125
                    int h = col >> 6, d = col & 63, p = d >> 1;
                    float c = freqs[l * 32 + p];
                    float s = freqs[SEQ * 32 + l * 32 + p];
                    float r0 = (v0 * c - v1 * s) * 0.125f;
                    float r1 = (v0 * s + v1 * c) * 0.125f;
                    *(uint32_t*)(g_qs + ((size_t)(b * NH + h) * SEQ + l) * 64 + d) = f2h2(r0, r1);
                } else if (col < 2560) {                  // k: rope
                    int kh = (col - 2048) >> 6, d = (col - 2048) & 63, p = d >> 1;
                    float c = freqs[l * 32 + p];
                    float s = freqs[SEQ * 32 + l * 32 + p];
                    float r0 = v0 * c - v1 * s;
                    float r1 = v0 * s + v1 * c;
                    *(uint32_t*)(g_ks + ((size_t)(b * NKV + kh) * SEQ + l) * 64 + d) = f2h2(r0, r1);
                } else {                                  // v: plain
                    int kh = (col - 2560) >> 6, d = (col - 2560) & 63;
                    *(uint32_t*)(g_vs + ((size_t)(b * NKV + kh) * SEQ + l) * 64 + d) = f2h2(v0, v1);
                }
            }
        }
    }
}

// ---------------------------------------------------------------------------
// Single-pass fp16 causal flash attention; epilogue writes g_at in
// A-fragment-packed layout (feeds O projection directly).
// grid (SEQ/128, NH, BB); 256 threads = 8 warps x 16 query rows.
// ---------------------------------------------------------------------------
constexpr int FA_STR = 144;
constexpr int FA_Q   = 0;                          // 18432 B
constexpr int FA_KV  = 128 * FA_STR;
constexpr int FA_SMEM = FA_KV + 4 * 64 * FA_STR;   // 55296
constexpr float LOG2E = 1.4426950408889634f;

__global__ __launch_bounds__(256, 2)
void flash_attn_f16(const __half* __restrict__ Qs,
                    const __half* __restrict__ Ks,
                    const __half* __restrict__ Vs) {
    extern __shared__ __align__(128) char fsm[];
    const uint32_t base = smem_u32(fsm);
    const uint32_t sQ = base + FA_Q;

    const int tid = threadIdx.x;
    const int wid = tid >> 5;
    const int L = tid & 31;
    const int wm = wid * 16;
    const uint32_t lrow = L & 15;
    const uint32_t lcol16 = (L >> 4) * 16;

    const int m0 = blockIdx.x * 128;
    const int h = blockIdx.y;
    const int b = blockIdx.z;
    const int kvh = h >> 2;

    const __half* qsrc = Qs + ((size_t)(b * NH + h) * SEQ + m0) * 64;
#pragma unroll
    for (int u = 0; u < 4; u++) {
        int e = tid + u * 256;
        int row = e >> 3, ch = e & 7;
        cp_async16(sQ + row * FA_STR + ch * 16, qsrc + (size_t)row * 64 + ch * 8);
    }
    cp_commit();
    asm volatile("cp.async.wait_group 0;" ::: "memory");
    __syncthreads();

    uint32_t qf[4][4];
#pragma unroll
    for (int kg = 0; kg < 4; kg++)
        ldm_x4(qf[kg], sQ + (wm + lrow) * FA_STR + kg * 32 + lcol16);

    float O[8][4];
#pragma unroll
    for (int i = 0; i < 8; i++)
#pragma unroll
        for (int j = 0; j < 4; j++) O[i][j] = 0.f;
    float mr0 = -1e30f, mr1 = -1e30f, lr0 = 0.f, lr1 = 0.f;

    const __half* ksrc = Ks + (size_t)(b * NKV + kvh) * SEQ * 64;
    const __half* vsrc = Vs + (size_t)(b * NKV + kvh) * SEQ * 64;

    auto load_kv = [&](int t) {
        const int n0 = t * 64;
        const uint32_t kb = base + FA_KV + (t & 1) * 18432;
        const uint32_t vb = kb + 9216;
#pragma unroll
        for (int u = 0; u < 2; u++) {
            int e = tid + u * 256;
            int row = e >> 3, ch = e & 7;
            cp_async16(kb + row * FA_STR + ch * 16, ksrc + (size_t)(n0 + row) * 64 + ch * 8);
            cp_async16(vb + row * FA_STR + ch * 16, vsrc + (size_t)(n0 + row) * 64 + ch * 8);
        }
    };

    const int nT = m0 / 64 + 2;
    load_kv(0); cp_commit();

    for (int t = 0; t < nT; t++) {
        if (t + 1 < nT) load_kv(t + 1);
        cp_commit();
        asm volatile("cp.async.wait_group 1;" ::: "memory");
        __syncthreads();

        const int n0 = t * 64;
        const uint32_t kb = base + FA_KV + (t & 1) * 18432;
        const uint32_t vb = kb + 9216;
        const bool active = (n0 <= m0 + wm + 15);

        if (active) {
            float S[8][4];
#pragma unroll
            for (int i = 0; i < 8; i++)
#pragma unroll
                for (int j = 0; j < 4; j++) S[i][j] = 0.f;

#pragma unroll
            for (int kg = 0; kg < 4; kg++) {
                uint32_t kf[4][4];
#pragma unroll
                for (int nn = 0; nn < 4; nn++)
                    ldm_x4(kf[nn], kb + (nn * 16 + lrow) * FA_STR + kg * 32 + lcol16);
#pragma unroll
                for (int ng = 0; ng < 8; ng++)
                    mma_f16(S[ng], qf[kg], kf[ng >> 1][ng & 1], kf[ng >> 1][2 + (ng & 1)]);
            }

            const int r0 = m0 + wm + (L >> 2);
            const int r1 = r0 + 8;
            if (n0 + 63 > m0 + wm) {
#pragma unroll
                for (int ng = 0; ng < 8; ng++) {
                    int c0 = n0 + ng * 8 + (L & 3) * 2;
                    if (c0 > r0)     S[ng][0] = -1e30f;
                    if (c0 + 1 > r0) S[ng][1] = -1e30f;
                    if (c0 > r1)     S[ng][2] = -1e30f;
                    if (c0 + 1 > r1) S[ng][3] = -1e30f;
                }
            }

            float t0 = -1e30f, t1 = -1e30f;
#pragma unroll
            for (int ng = 0; ng < 8; ng++) {
                t0 = fmaxf(t0, fmaxf(S[ng][0], S[ng][1]));
                t1 = fmaxf(t1, fmaxf(S[ng][2], S[ng][3]));
            }
            t0 = fmaxf(t0, __shfl_xor_sync(0xffffffffu, t0, 1));
            t0 = fmaxf(t0, __shfl_xor_sync(0xffffffffu, t0, 2));
            t1 = fmaxf(t1, __shfl_xor_sync(0xffffffffu, t1, 1));
            t1 = fmaxf(t1, __shfl_xor_sync(0xffffffffu, t1, 2));

            float mn0 = fmaxf(mr0, t0), mn1 = fmaxf(mr1, t1);
            float corr0 = ex2f((mr0 - mn0) * LOG2E);
            float corr1 = ex2f((mr1 - mn1) * LOG2E);
            lr0 *= corr0; lr1 *= corr1;
#pragma unroll
            for (int ng = 0; ng < 8; ng++) {
                O[ng][0] *= corr0; O[ng][1] *= corr0;
                O[ng][2] *= corr1; O[ng][3] *= corr1;
            }
            mr0 = mn0; mr1 = mn1;
            const float mb0 = mn0 * LOG2E, mb1 = mn1 * LOG2E;

            uint32_t pa[4][4];
            float s0 = 0.f, s1 = 0.f;
#pragma unroll
            for (int kg = 0; kg < 4; kg++) {
                float p[8];
#pragma unroll
                for (int e = 0; e < 2; e++) {
                    const int g = 2 * kg + e;
                    p[4 * e + 0] = ex2f(fmaf(S[g][0], LOG2E, -mb0));
                    p[4 * e + 1] = ex2f(fmaf(S[g][1], LOG2E, -mb0));
                    p[4 * e + 2] = ex2f(fmaf(S[g][2], LOG2E, -mb1));
                    p[4 * e + 3] = ex2f(fmaf(S[g][3], LOG2E, -mb1));
                    s0 += p[4 * e] + p[4 * e + 1];
                    s1 += p[4 * e + 2] + p[4 * e + 3];
                }
                pa[kg][0] = f2h2(p[0], p[1]);
                pa[kg][1] = f2h2(p[2], p[3]);
                pa[kg][2] = f2h2(p[4], p[5]);
                pa[kg][3] = f2h2(p[6], p[7]);
            }
            s0 += __shfl_xor_sync(0xffffffffu, s0, 1);
            s0 += __shfl_xor_sync(0xffffffffu, s0, 2);
            s1 += __shfl_xor_sync(0xffffffffu, s1, 1);
            s1 += __shfl_xor_sync(0xffffffffu, s1, 2);
            lr0 += s0; lr1 += s1;

#pragma unroll
            for (int kg = 0; kg < 4; kg++) {
                uint32_t vf[4][4];
#pragma unroll
                for (int cp = 0; cp < 4; cp++)
                    ldm_x4_t(vf[cp], vb + (kg * 16 + lrow) * FA_STR + cp * 32 + lcol16);
#pragma unroll
                for (int cp = 0; cp < 4; cp++) {
#pragma unroll
                    for (int e = 0; e < 2; e++) {
                        const int ng = 2 * cp + e;
                        mma_f16(O[ng], pa[kg], vf[cp][2 * e], vf[cp][2 * e + 1]);
                    }
                }
            }
        }
        __syncthreads();
    }

    // ---- epilogue: write A-fragment-packed fp16 into g_at ----
    const float inv0 = 1.f / lr0;
    const float inv1 = 1.f / lr1;
    const int mb = (b * SEQ + m0 + wm) >> 4;
#pragma unroll
    for (int ng = 0; ng < 8; ng++) {
        const int kc16 = h * 4 + (ng >> 1);
        uint32_t* w = g_at + ((size_t)(mb * 128 + kc16) * 32 + L) * 4 + (ng & 1) * 2;
        w[0] = f2h2(O[ng][0] * inv0, O[ng][1] * inv0);   // rows r, r (word a0/a2)
        w[1] = f2h2(O[ng][2] * inv1, O[ng][3] * inv1);   // rows r+8   (word a1/a3)
    }
}

// ---------------------------------------------------------------------------
extern "C" void kernel_launch(void* const* d_in, const int* in_sizes, int n_in,
                              void* d_out, int out_size) {
    const float* x     = (const float*)d_in[0];
    const float* freqs = (const float*)d_in[1];
    const float* wq    = (const float*)d_in[2];
    const float* wk    = (const float*)d_in[3];
    const float* wv    = (const float*)d_in[4];
    const float* wo    = (const float*)d_in[5];
    float* out = (float*)d_out;

    uint32_t *xt, *wqkvt, *wot, *at;
    __half *qs, *ks, *vs;
    cudaGetSymbolAddress((void**)&xt, g_xt);
    cudaGetSymbolAddress((void**)&wqkvt, g_wqkvt);
    cudaGetSymbolAddress((void**)&wot, g_wot);
    cudaGetSymbolAddress((void**)&at, g_at);
    cudaGetSymbolAddress((void**)&qs, g_qs);
    cudaGetSymbolAddress((void**)&ks, g_ks);
    cudaGetSymbolAddress((void**)&vs, g_vs);

    static bool attr_done = false;
    if (!attr_done) {
        cudaFuncSetAttribute(gemm_f16, cudaFuncAttributeMaxDynamicSharedMemorySize, GSMEM);
        cudaFuncSetAttribute(gemm_qkv, cudaFuncAttributeMaxDynamicSharedMemorySize, GSMEM);
        cudaFuncSetAttribute(flash_attn_f16, cudaFuncAttributeMaxDynamicSharedMemorySize, FA_SMEM);
        attr_done = true;
    }

    // 1) pack x, 2) pack merged qkv weights, 3) pack wo
    pack_a<<<4096, 256>>>(x, xt, 0, 256);
    pack_b_qkv<<<(NQKV * 256) / 256, 256>>>(wq, wk, wv, wqkvt, NQKV * 256);
    pack_b<<<(DIMM * 256) / 256, 256>>>(wo, wot, DIMM * 256);

    // 4) fused QKV projection + RoPE + fp16 -> g_qs/g_ks/g_vs
    gemm_qkv<<<dim3(NQKV / 128, MROWS / 128), 256, GSMEM>>>(xt, wqkvt, freqs);

    // 5) fp16 attention -> fragment-packed g_at
    flash_attn_f16<<<dim3(SEQ / 128, NH, BB), 256, FA_SMEM>>>(qs, ks, vs);

    // 6) O projection -> d_out
    gemm_f16<<<dim3(DIMM / 128, MROWS / 128), 256, GSMEM>>>(at, wot, out, DIMM);
}

// round 11
// speedup vs baseline: 3.5241x; 1.0095x over previous
#include <cuda_runtime.h>
#include <cuda_fp16.h>
#include <cstdint>
#include <cstddef>

// Problem constants
constexpr int BB   = 2;
constexpr int SEQ  = 2048;
constexpr int DIMM = 2048;
constexpr int NH   = 32;
constexpr int NKV  = 8;
constexpr int HDIM = 64;
constexpr int MROWS = BB * SEQ;                    // 4096
constexpr int NQKV  = NH * HDIM + 2 * NKV * HDIM;  // 3072

// ---------------------------------------------------------------------------
// Scratch (device globals; allocation-free rule)
// Fragment-packed fp16 operands (m16n8k16):
//  A-pack: [mb=row/16][kc16=k/16 (128)][lane][4 half2 words]
//  B-pack: [nb=n/8][kc32=k/32 (64)][lane][4 half2 words]
// ---------------------------------------------------------------------------
__device__ uint32_t g_xt[MROWS * DIMM / 2];         // packed x           16 MB
__device__ uint32_t g_wqkvt[NQKV * DIMM / 2];       // packed wq|wk|wv    12 MB
__device__ uint32_t g_wot[DIMM * DIMM / 2];         // packed wo           8 MB
__device__ uint32_t g_at[MROWS * DIMM / 2];         // packed attn out    16 MB
// attention inputs, fp16, 64 per row
__device__ __half g_qs[BB * NH * SEQ * HDIM];       // 16 MB (q roped, /8)
__device__ __half g_ks[BB * NKV * SEQ * HDIM];      // 4 MB  (k roped)
__device__ __half g_vs[BB * NKV * SEQ * HDIM];      // 4 MB

// ---------------------------------------------------------------------------
// Helpers
// ---------------------------------------------------------------------------
__device__ __forceinline__ uint32_t smem_u32(const void* p) {
    uint32_t a;
    asm("{ .reg .u64 t; cvta.to.shared.u64 t, %1; cvt.u32.u64 %0, t; }" : "=r"(a) : "l"(p));
    return a;
}
__device__ __forceinline__ void cp_async16(uint32_t dst, const void* src) {
    asm volatile("cp.async.cg.shared.global [%0], [%1], 16;" :: "r"(dst), "l"(src));
}
__device__ __forceinline__ void cp_commit() { asm volatile("cp.async.commit_group;" ::: "memory"); }

__device__ __forceinline__ void lds128(uint32_t* r, uint32_t addr) {
    asm volatile("ld.shared.v4.b32 {%0,%1,%2,%3}, [%4];"
        : "=r"(r[0]), "=r"(r[1]), "=r"(r[2]), "=r"(r[3]) : "r"(addr));
}
__device__ __forceinline__ void ldm_x4(uint32_t* r, uint32_t addr) {
    asm volatile("ldmatrix.sync.aligned.m8n8.x4.shared.b16 {%0,%1,%2,%3}, [%4];"
        : "=r"(r[0]), "=r"(r[1]), "=r"(r[2]), "=r"(r[3]) : "r"(addr));
}
__device__ __forceinline__ void ldm_x4_t(uint32_t* r, uint32_t addr) {
    asm volatile("ldmatrix.sync.aligned.m8n8.x4.trans.shared.b16 {%0,%1,%2,%3}, [%4];"
        : "=r"(r[0]), "=r"(r[1]), "=r"(r[2]), "=r"(r[3]) : "r"(addr));
}
__device__ __forceinline__ void mma_f16(float* d, const uint32_t* a, uint32_t b0, uint32_t b1) {
    asm volatile("mma.sync.aligned.m16n8k16.row.col.f32.f16.f16.f32 "
        "{%0,%1,%2,%3}, {%4,%5,%6,%7}, {%8,%9}, {%0,%1,%2,%3};"
        : "+f"(d[0]), "+f"(d[1]), "+f"(d[2]), "+f"(d[3])
        : "r"(a[0]), "r"(a[1]), "r"(a[2]), "r"(a[3]), "r"(b0), "r"(b1));
}
__device__ __forceinline__ uint32_t f2h2(float lo, float hi) {
    __half2 h = __floats2half2_rn(lo, hi);
    return *(uint32_t*)&h;
}
__device__ __forceinline__ float ex2f(float x) {
    float r;
    asm("ex2.approx.f32 %0, %1;" : "=f"(r) : "f"(x));
    return r;
}

// ---------------------------------------------------------------------------
// pack_a: fp32 [rows][2048] -> fp16 A-fragment pack (m16n8k16).
// ---------------------------------------------------------------------------
__global__ __launch_bounds__(256) void pack_a(const float* __restrict__ src,
                                              uint32_t* __restrict__ dst,
                                              int mb0, int nmb) {
    int idx = blockIdx.x * 256 + threadIdx.x;
    if (idx >= nmb * 4096) return;
    int lane = idx & 31;
    int kc16 = (idx >> 5) & 127;
    int mb = (idx >> 12) + mb0;
    int r = lane >> 2;
    int c2 = kc16 * 16 + (lane & 3) * 2;
    const float* s = src + (size_t)mb * 16 * 2048;
    uint4 o;
    o.x = f2h2(s[(size_t)r * 2048 + c2],        s[(size_t)r * 2048 + c2 + 1]);
    o.y = f2h2(s[(size_t)(r + 8) * 2048 + c2],  s[(size_t)(r + 8) * 2048 + c2 + 1]);
    o.z = f2h2(s[(size_t)r * 2048 + c2 + 8],    s[(size_t)r * 2048 + c2 + 9]);
    o.w = f2h2(s[(size_t)(r + 8) * 2048 + c2 + 8], s[(size_t)(r + 8) * 2048 + c2 + 9]);
    ((uint4*)dst)[(size_t)mb * 4096 + (idx & 4095)] = o;
}

// ---------------------------------------------------------------------------
// pack_b: weights [N][2048] -> fp16 B-fragment pack.
// ---------------------------------------------------------------------------
__global__ __launch_bounds__(256) void pack_b(const float* __restrict__ src,
                                              uint32_t* __restrict__ dst, int total) {
    int idx = blockIdx.x * 256 + threadIdx.x;
    if (idx >= total) return;
    int lane = idx & 31;
    int kc32 = (idx >> 5) & 63;
    int nb = idx >> 11;
    int n = nb * 8 + (lane >> 2);
    int k2 = kc32 * 32 + (lane & 3) * 2;
    const float* s = src + (size_t)n * 2048 + k2;
    uint4 o;
    o.x = f2h2(s[0],  s[1]);
    o.y = f2h2(s[8],  s[9]);
    o.z = f2h2(s[16], s[17]);
    o.w = f2h2(s[24], s[25]);
    ((uint4*)dst)[idx] = o;
}

__global__ __launch_bounds__(256) void pack_b_qkv(const float* __restrict__ wq,
                                                  const float* __restrict__ wk,
                                                  const float* __restrict__ wv,
                                                  uint32_t* __restrict__ dst, int total) {
    int idx = blockIdx.x * 256 + threadIdx.x;
    if (idx >= total) return;
    int lane = idx & 31;
    int kc32 = (idx >> 5) & 63;
    int nb = idx >> 11;
    int n = nb * 8 + (lane >> 2);
    int k2 = kc32 * 32 + (lane & 3) * 2;
    const float* s;
    if (n < 2048)      s = wq + (size_t)n * 2048 + k2;
    else if (n < 2560) s = wk + (size_t)(n - 2048) * 2048 + k2;
    else               s = wv + (size_t)(n - 2560) * 2048 + k2;
    uint4 o;
    o.x = f2h2(s[0],  s[1]);
    o.y = f2h2(s[8],  s[9]);
    o.z = f2h2(s[16], s[17]);
    o.w = f2h2(s[24], s[25]);
    ((uint4*)dst)[idx] = o;
}

// ---------------------------------------------------------------------------
// GEMM mainloop: CTA 128x128, 128 threads = 4 warps (2x2), warp tile 64x64,
// K-chunk 32, 3-stage cp.async pipeline (16KB/stage), 2 CTAs/SM.
// ---------------------------------------------------------------------------
constexpr int FSTAGE = 16384;
constexpr int GSMEM  = 3 * FSTAGE;                 // 49152

struct GemmCtx {
    float acc[4][8][4];
    int bm, bn, wid, L;
};

__device__ __forceinline__ void gemm_mainloop(const uint32_t* __restrict__ A,
                                              const uint32_t* __restrict__ B,
                                              GemmCtx& cx, char* dsm) {
    const int tid = threadIdx.x;
    const int wid = tid >> 5;
    const int L = tid & 31;
    const uint32_t base = smem_u32(dsm);
    cx.bm = blockIdx.y * 128;
    cx.bn = blockIdx.x * 128;
    cx.wid = wid; cx.L = L;
    const uint32_t* Ab = A + (size_t)(cx.bm >> 4) * 16384;
    const uint32_t* Bb = B + (size_t)(cx.bn >> 3) * 8192;

#pragma unroll
    for (int i = 0; i < 4; i++)
#pragma unroll
        for (int j = 0; j < 8; j++)
#pragma unroll
            for (int q = 0; q < 4; q++) cx.acc[i][j][q] = 0.f;

    auto load_stage = [&](int s, int c) {
        const uint32_t sb = base + s * FSTAGE;
#pragma unroll
        for (int u = 0; u < 4; u++) {            // A: 512 uint4
            int e = tid + u * 128;
            int lane = e & 31, kcl = (e >> 5) & 1, mb = e >> 6;
            cp_async16(sb + e * 16,
                       Ab + (((size_t)mb * 128 + c * 2 + kcl) * 32 + lane) * 4);
        }
#pragma unroll
        for (int u = 0; u < 4; u++) {            // B: 512 uint4
            int e = tid + u * 128;
            int lane = e & 31, nb = e >> 5;
            cp_async16(sb + 8192 + e * 16,
                       Bb + (((size_t)nb * 64 + c) * 32 + lane) * 4);
        }
    };

    load_stage(0, 0); cp_commit();
    load_stage(1, 1); cp_commit();

    const int wmb = (wid >> 1) * 4;     // warp A mb base (m/16)
    const int wnb = (wid & 1) * 8;      // warp B nb base (n/8)

    for (int i = 0; i < 64; i++) {
        asm volatile("cp.async.wait_group 1;" ::: "memory");
        __syncthreads();
        if (i + 2 < 64) load_stage((i + 2) % 3, i + 2);
        cp_commit();

        const uint32_t sA = base + (i % 3) * FSTAGE;
        const uint32_t sB = sA + 8192;
        uint32_t b[8][4];
#pragma unroll
        for (int g = 0; g < 8; g++)
            lds128(b[g], sB + ((wnb + g) * 32 + L) * 16);
#pragma unroll
        for (int kcl = 0; kcl < 2; kcl++) {
            uint32_t a[4][4];
#pragma unroll
            for (int am = 0; am < 4; am++)
                lds128(a[am], sA + (((wmb + am) * 2 + kcl) * 32 + L) * 16);
#pragma unroll
            for (int am = 0; am < 4; am++)
#pragma unroll
                for (int g = 0; g < 8; g++)
                    mma_f16(cx.acc[am][g], a[am], b[g][2 * kcl], b[g][2 * kcl + 1]);
        }
    }
}

// ---------------------------------------------------------------------------
// O-projection GEMM: plain fp32 epilogue to d_out.
// ---------------------------------------------------------------------------
__global__ __launch_bounds__(128, 2)
void gemm_f16(const uint32_t* __restrict__ A, const uint32_t* __restrict__ B,
              float* __restrict__ C, int Ntot) {
    extern __shared__ __align__(128) char dsm[];
    GemmCtx cx;
    gemm_mainloop(A, B, cx, dsm);
#pragma unroll
    for (int am = 0; am < 4; am++) {
        int row = cx.bm + (cx.wid >> 1) * 64 + am * 16 + (cx.L >> 2);
#pragma unroll
        for (int g = 0; g < 8; g++) {
            int col = cx.bn + (cx.wid & 1) * 64 + g * 8 + (cx.L & 3) * 2;
            *(float2*)(C + (size_t)row * Ntot + col) = make_float2(cx.acc[am][g][0], cx.acc[am][g][1]);
            *(float2*)(C + (size_t)(row + 8) * Ntot + col) = make_float2(cx.acc[am][g][2], cx.acc[am][g][3]);
        }
    }
}

// ---------------------------------------------------------------------------
// QKV GEMM with fused RoPE + fp16 epilogue writing g_qs/g_ks/g_vs.
// ---------------------------------------------------------------------------
__global__ __launch_bounds__(128, 2)
void gemm_qkv(const uint32_t* __restrict__ A, const uint32_t* __restrict__ B,
              const float* __restrict__ freqs) {
    extern __shared__ __align__(128) char dsm[];
    GemmCtx cx;
    gemm_mainloop(A, B, cx, dsm);

#pragma unroll
    for (int am = 0; am < 4; am++) {
        int row0 = cx.bm + (cx.wid >> 1) * 64 + am * 16 + (cx.L >> 2);
#pragma unroll
        for (int half = 0; half < 2; half++) {
            const int row = row0 + half * 8;
            const int l = row & (SEQ - 1);
            const int b = row >> 11;
#pragma unroll
            for (int g = 0; g < 8; g++) {
                int col = cx.bn + (cx.wid & 1) * 64 + g * 8 + (cx.L & 3) * 2;
                float v0 = cx.acc[am][g][2 * half];
                float v1 = cx.acc[am][g][2 * half + 1];
                if (col < 2048) {                         // q: rope + 0.125
                    int h = col >> 6, d = col & 63, p = d >> 1;
                    float c = freqs[l * 32 + p];
                    float s = freqs[SEQ * 32 + l * 32 + p];
                    float r0 = (v0 * c - v1 * s) * 0.125f;
                    float r1 = (v0 * s + v1 * c) * 0.125f;
                    *(uint32_t*)(g_qs + ((size_t)(b * NH + h) * SEQ + l) * 64 + d) = f2h2(r0, r1);
                } else if (col < 2560) {                  // k: rope
                    int kh = (col - 2048) >> 6, d = (col - 2048) & 63, p = d >> 1;
                    float c = freqs[l * 32 + p];
                    float s = freqs[SEQ * 32 + l * 32 + p];
                    float r0 = v0 * c - v1 * s;
                    float r1 = v0 * s + v1 * c;
                    *(uint32_t*)(g_ks + ((size_t)(b * NKV + kh) * SEQ + l) * 64 + d) = f2h2(r0, r1);
                } else {                                  // v: plain
                    int kh = (col - 2560) >> 6, d = (col - 2560) & 63;
                    *(uint32_t*)(g_vs + ((size_t)(b * NKV + kh) * SEQ + l) * 64 + d) = f2h2(v0, v1);
                }
            }
        }
    }
}

// ---------------------------------------------------------------------------
// Single-pass fp16 causal flash attention; epilogue writes g_at in
// A-fragment-packed layout (feeds O projection directly).
// grid (SEQ/128, NH, BB); 256 threads = 8 warps x 16 query rows.
// ---------------------------------------------------------------------------
constexpr int FA_STR = 144;
constexpr int FA_Q   = 0;                          // 18432 B
constexpr int FA_KV  = 128 * FA_STR;
constexpr int FA_SMEM = FA_KV + 4 * 64 * FA_STR;   // 55296
constexpr float LOG2E = 1.4426950408889634f;

__global__ __launch_bounds__(256, 2)
void flash_attn_f16(const __half* __restrict__ Qs,
                    const __half* __restrict__ Ks,
                    const __half* __restrict__ Vs) {
    extern __shared__ __align__(128) char fsm[];
    const uint32_t base = smem_u32(fsm);
    const uint32_t sQ = base + FA_Q;

    const int tid = threadIdx.x;
    const int wid = tid >> 5;
    const int L = tid & 31;
    const int wm = wid * 16;
    const uint32_t lrow = L & 15;
    const uint32_t lcol16 = (L >> 4) * 16;

    const int m0 = blockIdx.x * 128;
    const int h = blockIdx.y;
    const int b = blockIdx.z;
    const int kvh = h >> 2;

    const __half* qsrc = Qs + ((size_t)(b * NH + h) * SEQ + m0) * 64;
#pragma unroll
    for (int u = 0; u < 4; u++) {
        int e = tid + u * 256;
        int row = e >> 3, ch = e & 7;
        cp_async16(sQ + row * FA_STR + ch * 16, qsrc + (size_t)row * 64 + ch * 8);
    }
    cp_commit();
    asm volatile("cp.async.wait_group 0;" ::: "memory");
    __syncthreads();

    uint32_t qf[4][4];
#pragma unroll
    for (int kg = 0; kg < 4; kg++)
        ldm_x4(qf[kg], sQ + (wm + lrow) * FA_STR + kg * 32 + lcol16);

    float O[8][4];
#pragma unroll
    for (int i = 0; i < 8; i++)
#pragma unroll
        for (int j = 0; j < 4; j++) O[i][j] = 0.f;
    float mr0 = -1e30f, mr1 = -1e30f, lr0 = 0.f, lr1 = 0.f;

    const __half* ksrc = Ks + (size_t)(b * NKV + kvh) * SEQ * 64;
    const __half* vsrc = Vs + (size_t)(b * NKV + kvh) * SEQ * 64;

    auto load_kv = [&](int t) {
        const int n0 = t * 64;
        const uint32_t kb = base + FA_KV + (t & 1) * 18432;
        const uint32_t vb = kb + 9216;
#pragma unroll
        for (int u = 0; u < 2; u++) {
            int e = tid + u * 256;
            int row = e >> 3, ch = e & 7;
            cp_async16(kb + row * FA_STR + ch * 16, ksrc + (size_t)(n0 + row) * 64 + ch * 8);
            cp_async16(vb + row * FA_STR + ch * 16, vsrc + (size_t)(n0 + row) * 64 + ch * 8);
        }
    };

    const int nT = m0 / 64 + 2;
    load_kv(0); cp_commit();

    for (int t = 0; t < nT; t++) {
        if (t + 1 < nT) load_kv(t + 1);
        cp_commit();
        asm volatile("cp.async.wait_group 1;" ::: "memory");
        __syncthreads();

        const int n0 = t * 64;
        const uint32_t kb = base + FA_KV + (t & 1) * 18432;
        const uint32_t vb = kb + 9216;
        const bool active = (n0 <= m0 + wm + 15);

        if (active) {
            float S[8][4];
#pragma unroll
            for (int i = 0; i < 8; i++)
#pragma unroll
                for (int j = 0; j < 4; j++) S[i][j] = 0.f;

#pragma unroll
            for (int kg = 0; kg < 4; kg++) {
                uint32_t kf[4][4];
#pragma unroll
                for (int nn = 0; nn < 4; nn++)
                    ldm_x4(kf[nn], kb + (nn * 16 + lrow) * FA_STR + kg * 32 + lcol16);
#pragma unroll
                for (int ng = 0; ng < 8; ng++)
                    mma_f16(S[ng], qf[kg], kf[ng >> 1][ng & 1], kf[ng >> 1][2 + (ng & 1)]);
            }

            const int r0 = m0 + wm + (L >> 2);
            const int r1 = r0 + 8;
            if (n0 + 63 > m0 + wm) {
#pragma unroll
                for (int ng = 0; ng < 8; ng++) {
                    int c0 = n0 + ng * 8 + (L & 3) * 2;
                    if (c0 > r0)     S[ng][0] = -1e30f;
                    if (c0 + 1 > r0) S[ng][1] = -1e30f;
                    if (c0 > r1)     S[ng][2] = -1e30f;
                    if (c0 + 1 > r1) S[ng][3] = -1e30f;
                }
            }

            float t0 = -1e30f, t1 = -1e30f;
#pragma unroll
            for (int ng = 0; ng < 8; ng++) {
                t0 = fmaxf(t0, fmaxf(S[ng][0], S[ng][1]));
                t1 = fmaxf(t1, fmaxf(S[ng][2], S[ng][3]));
            }
            t0 = fmaxf(t0, __shfl_xor_sync(0xffffffffu, t0, 1));
            t0 = fmaxf(t0, __shfl_xor_sync(0xffffffffu, t0, 2));
            t1 = fmaxf(t1, __shfl_xor_sync(0xffffffffu, t1, 1));
            t1 = fmaxf(t1, __shfl_xor_sync(0xffffffffu, t1, 2));

            float mn0 = fmaxf(mr0, t0), mn1 = fmaxf(mr1, t1);
            float corr0 = ex2f((mr0 - mn0) * LOG2E);
            float corr1 = ex2f((mr1 - mn1) * LOG2E);
            lr0 *= corr0; lr1 *= corr1;
#pragma unroll
            for (int ng = 0; ng < 8; ng++) {
                O[ng][0] *= corr0; O[ng][1] *= corr0;
                O[ng][2] *= corr1; O[ng][3] *= corr1;
            }
            mr0 = mn0; mr1 = mn1;
            const float mb0 = mn0 * LOG2E, mb1 = mn1 * LOG2E;

            uint32_t pa[4][4];
            float s0 = 0.f, s1 = 0.f;
#pragma unroll
            for (int kg = 0; kg < 4; kg++) {
                float p[8];
#pragma unroll
                for (int e = 0; e < 2; e++) {
                    const int g = 2 * kg + e;
                    p[4 * e + 0] = ex2f(fmaf(S[g][0], LOG2E, -mb0));
                    p[4 * e + 1] = ex2f(fmaf(S[g][1], LOG2E, -mb0));
                    p[4 * e + 2] = ex2f(fmaf(S[g][2], LOG2E, -mb1));
                    p[4 * e + 3] = ex2f(fmaf(S[g][3], LOG2E, -mb1));
                    s0 += p[4 * e] + p[4 * e + 1];
                    s1 += p[4 * e + 2] + p[4 * e + 3];
                }
                pa[kg][0] = f2h2(p[0], p[1]);
                pa[kg][1] = f2h2(p[2], p[3]);
                pa[kg][2] = f2h2(p[4], p[5]);
                pa[kg][3] = f2h2(p[6], p[7]);
            }
            s0 += __shfl_xor_sync(0xffffffffu, s0, 1);
            s0 += __shfl_xor_sync(0xffffffffu, s0, 2);
            s1 += __shfl_xor_sync(0xffffffffu, s1, 1);
            s1 += __shfl_xor_sync(0xffffffffu, s1, 2);
            lr0 += s0; lr1 += s1;

#pragma unroll
            for (int kg = 0; kg < 4; kg++) {
                uint32_t vf[4][4];
#pragma unroll
                for (int cp = 0; cp < 4; cp++)
                    ldm_x4_t(vf[cp], vb + (kg * 16 + lrow) * FA_STR + cp * 32 + lcol16);
#pragma unroll
                for (int cp = 0; cp < 4; cp++) {
#pragma unroll
                    for (int e = 0; e < 2; e++) {
                        const int ng = 2 * cp + e;
                        mma_f16(O[ng], pa[kg], vf[cp][2 * e], vf[cp][2 * e + 1]);
                    }
                }
            }
        }
        __syncthreads();
    }

    // ---- epilogue: write A-fragment-packed fp16 into g_at ----
    const float inv0 = 1.f / lr0;
    const float inv1 = 1.f / lr1;
    const int mb = (b * SEQ + m0 + wm) >> 4;
#pragma unroll
    for (int ng = 0; ng < 8; ng++) {
        const int kc16 = h * 4 + (ng >> 1);
        uint32_t* w = g_at + ((size_t)(mb * 128 + kc16) * 32 + L) * 4 + (ng & 1) * 2;
        w[0] = f2h2(O[ng][0] * inv0, O[ng][1] * inv0);
        w[1] = f2h2(O[ng][2] * inv1, O[ng][3] * inv1);
    }
}

// ---------------------------------------------------------------------------
extern "C" void kernel_launch(void* const* d_in, const int* in_sizes, int n_in,
                              void* d_out, int out_size) {
    const float* x     = (const float*)d_in[0];
    const float* freqs = (const float*)d_in[1];
    const float* wq    = (const float*)d_in[2];
    const float* wk    = (const float*)d_in[3];
    const float* wv    = (const float*)d_in[4];
    const float* wo    = (const float*)d_in[5];
    float* out = (float*)d_out;

    uint32_t *xt, *wqkvt, *wot, *at;
    __half *qs, *ks, *vs;
    cudaGetSymbolAddress((void**)&xt, g_xt);
    cudaGetSymbolAddress((void**)&wqkvt, g_wqkvt);
    cudaGetSymbolAddress((void**)&wot, g_wot);
    cudaGetSymbolAddress((void**)&at, g_at);
    cudaGetSymbolAddress((void**)&qs, g_qs);
    cudaGetSymbolAddress((void**)&ks, g_ks);
    cudaGetSymbolAddress((void**)&vs, g_vs);

    static bool attr_done = false;
    if (!attr_done) {
        cudaFuncSetAttribute(gemm_f16, cudaFuncAttributeMaxDynamicSharedMemorySize, GSMEM);
        cudaFuncSetAttribute(gemm_qkv, cudaFuncAttributeMaxDynamicSharedMemorySize, GSMEM);
        cudaFuncSetAttribute(flash_attn_f16, cudaFuncAttributeMaxDynamicSharedMemorySize, FA_SMEM);
        attr_done = true;
    }

    // 1) pack x, 2) pack merged qkv weights, 3) pack wo
    pack_a<<<4096, 256>>>(x, xt, 0, 256);
    pack_b_qkv<<<(NQKV * 256) / 256, 256>>>(wq, wk, wv, wqkvt, NQKV * 256);
    pack_b<<<(DIMM * 256) / 256, 256>>>(wo, wot, DIMM * 256);

    // 4) fused QKV projection + RoPE + fp16 -> g_qs/g_ks/g_vs
    gemm_qkv<<<dim3(NQKV / 128, MROWS / 128), 128, GSMEM>>>(xt, wqkvt, freqs);

    // 5) fp16 attention -> fragment-packed g_at
    flash_attn_f16<<<dim3(SEQ / 128, NH, BB), 256, FA_SMEM>>>(qs, ks, vs);

    // 6) O projection -> d_out
    gemm_f16<<<dim3(DIMM / 128, MROWS / 128), 128, GSMEM>>>(at, wot, out, DIMM);
}